// round 6
// baseline (speedup 1.0000x reference)
#include <cuda_runtime.h>
#include <cuda_bf16.h>
#include <math.h>
#include <stdint.h>

// ---------------- problem constants ----------------
#define BN    48
#define CCH   128
#define NWIN  49
#define NTOK  49
#define MROWS (BN*NWIN*NTOK)   // 115248
#define HID   512
#define QSCALE 0.17677669529663687f

// ---------------- scratch (device globals) ----------------
__device__ __nv_bfloat16 g_xw [(size_t)MROWS*CCH];   // LN1 out -> attn out (window order)
__device__ __nv_bfloat16 g_ln2[(size_t)MROWS*CCH];   // LN2 out (x layout)  [fc1 input]
__device__ __nv_bfloat16 g_big[(size_t)MROWS*HID];   // qkv (stride 384) then hidden (stride 512)
__device__ float         g_x2 [(size_t)MROWS*CCH];   // fp32 residual (x layout)
__device__ __nv_bfloat16 g_wts[196608];
__device__ float         g_bm [49*4*64*64];
#define WOFF_QKV 0
#define WOFF_PROJ 49152
#define WOFF_FC1  65536
#define WOFF_FC2  131072

// ---------------- asm helpers ----------------
__device__ __forceinline__ uint32_t smem_u32(const void* p) {
    return (uint32_t)__cvta_generic_to_shared(p);
}
__device__ __forceinline__ void cp_async16(uint32_t dst, const void* src, int sz) {
    asm volatile("cp.async.cg.shared.global [%0], [%1], 16, %2;"
                 :: "r"(dst), "l"(src), "r"(sz));
}
__device__ __forceinline__ void ldsm_x4(uint32_t r[4], uint32_t addr) {
    asm volatile("ldmatrix.sync.aligned.m8n8.x4.shared.b16 {%0,%1,%2,%3}, [%4];"
                 : "=r"(r[0]), "=r"(r[1]), "=r"(r[2]), "=r"(r[3]) : "r"(addr));
}
__device__ __forceinline__ void ldsm_x4_t(uint32_t r[4], uint32_t addr) {
    asm volatile("ldmatrix.sync.aligned.m8n8.x4.trans.shared.b16 {%0,%1,%2,%3}, [%4];"
                 : "=r"(r[0]), "=r"(r[1]), "=r"(r[2]), "=r"(r[3]) : "r"(addr));
}
__device__ __forceinline__ void mma_bf16(float c[4], const uint32_t a[4],
                                         uint32_t b0, uint32_t b1) {
    asm volatile("mma.sync.aligned.m16n8k16.row.col.f32.bf16.bf16.f32 "
                 "{%0,%1,%2,%3}, {%4,%5,%6,%7}, {%8,%9}, {%0,%1,%2,%3};"
                 : "+f"(c[0]), "+f"(c[1]), "+f"(c[2]), "+f"(c[3])
                 : "r"(a[0]), "r"(a[1]), "r"(a[2]), "r"(a[3]), "r"(b0), "r"(b1));
}

// ---------------- weight convert ----------------
__global__ void cvt_weights(const float* __restrict__ qkv_w, const float* __restrict__ proj_w,
                            const float* __restrict__ fc1_w, const float* __restrict__ fc2_w) {
    int i = blockIdx.x * 256 + threadIdx.x;
    if (i < 49152)       g_wts[WOFF_QKV  + i] = __float2bfloat16_rn(qkv_w[i]);
    if (i < 16384)       g_wts[WOFF_PROJ + i] = __float2bfloat16_rn(proj_w[i]);
    if (i < 65536) {     g_wts[WOFF_FC1  + i] = __float2bfloat16_rn(fc1_w[i]);
                         g_wts[WOFF_FC2  + i] = __float2bfloat16_rn(fc2_w[i]); }
}

// ---------------- bias+mask table ----------------
__device__ __forceinline__ int regn(int wq, int iq) {
    return (wq < 6) ? 0 : ((iq < 4) ? 1 : 2);
}
__global__ void build_bm(const float* __restrict__ rpb) {
    int w = blockIdx.x, h = blockIdx.y;
    int wh = w / 7, ww = w % 7;
    for (int e = threadIdx.x; e < 64 * 64; e += 256) {
        int n = e >> 6, m = e & 63;
        float v;
        if (n < 49 && m < 49) {
            int i1 = n / 7, j1 = n % 7, i2 = m / 7, j2 = m % 7;
            v = rpb[((i1 - i2 + 6) * 13 + (j1 - j2 + 6)) * 4 + h];
            int mwW = regn(wh, i2) * 3 + regn(ww, j2);
            int mwN = regn(i1, i2) * 3 + regn(j1, j2);
            if (mwW != mwN) v -= 100.f;
        } else {
            v = -1e9f;
        }
        g_bm[((size_t)(w * 4 + h) * 64 + n) * 64 + m] = v;
    }
}

// ---------------- LN1 + shift + window gather ----------------
__global__ void ln1_gather_kernel(const float* __restrict__ x,
                                  const float* __restrict__ w,
                                  const float* __restrict__ b) {
    int t = blockIdx.x, c = threadIdx.x;
    int bw = t / NTOK, n = t - bw * NTOK;
    int bb = bw / NWIN, wi = bw - bb * NWIN;
    int R  = (wi / 7) * 7 + n / 7;
    int Cl = (wi % 7) * 7 + n % 7;
    int sr = R + 3;  if (sr >= 49) sr -= 49;
    int sc = Cl + 3; if (sc >= 49) sc -= 49;
    float v = x[((size_t)bb * 2401 + sr * 49 + sc) * CCH + c];
    float s = v, s2 = v * v;
    #pragma unroll
    for (int o = 16; o > 0; o >>= 1) {
        s  += __shfl_xor_sync(0xffffffffu, s,  o);
        s2 += __shfl_xor_sync(0xffffffffu, s2, o);
    }
    __shared__ float red[8];
    int wid = c >> 5, lane = c & 31;
    if (lane == 0) { red[wid] = s; red[4 + wid] = s2; }
    __syncthreads();
    float ts  = red[0] + red[1] + red[2] + red[3];
    float ts2 = red[4] + red[5] + red[6] + red[7];
    float mean = ts * (1.f / 128.f);
    float var  = ts2 * (1.f / 128.f) - mean * mean;
    float rstd = rsqrtf(var + 1e-5f);
    g_xw[(size_t)t * CCH + c] = __float2bfloat16_rn((v - mean) * rstd * w[c] + b[c]);
}

// ---------------- tensor-core attention ----------------
__global__ void __launch_bounds__(128) attn_kernel() {
    int bw = blockIdx.x, h = blockIdx.y;
    int w  = bw % NWIN;
    int tid = threadIdx.x, lane = tid & 31, warp = tid >> 5;

    __shared__ __align__(16) uint8_t sQ[64 * 64];
    __shared__ __align__(16) uint8_t sK[64 * 64];
    __shared__ __align__(16) uint8_t sV[64 * 64];
    __shared__ __align__(16) uint8_t sP[64 * 128];

    uint32_t qb = smem_u32(sQ), kb = smem_u32(sK);
    uint32_t vb = smem_u32(sV), pb = smem_u32(sP);

    const __nv_bfloat16* base = g_big + (size_t)bw * NTOK * 384;
    for (int id = tid; id < 768; id += 128) {
        int op = id >> 8;
        int r  = (id >> 2) & 63;
        int c  = id & 3;
        uint32_t sb = (op == 0) ? qb : (op == 1) ? kb : vb;
        uint32_t dst = sb + r * 64 + ((c ^ ((r >> 1) & 3)) << 4);
        const __nv_bfloat16* src = base + (r < 49 ? r : 0) * 384 + op * 128 + h * 32 + c * 8;
        cp_async16(dst, src, r < 49 ? 16 : 0);
    }
    asm volatile("cp.async.commit_group;");
    asm volatile("cp.async.wait_group 0;");
    __syncthreads();

    int g = lane >> 2, tg = lane & 3;
    int m0 = warp * 16;

    float acc[8][4];
    #pragma unroll
    for (int i = 0; i < 8; i++)
        #pragma unroll
        for (int j = 0; j < 4; j++) acc[i][j] = 0.f;

    #pragma unroll
    for (int ks = 0; ks < 2; ks++) {
        uint32_t aF[4];
        {
            int r = m0 + (lane & 15);
            int c = 2 * ks + (lane >> 4);
            ldsm_x4(aF, qb + r * 64 + ((c ^ ((r >> 1) & 3)) << 4));
        }
        #pragma unroll
        for (int nfp = 0; nfp < 4; nfp++) {
            uint32_t bF[4];
            int r = nfp * 16 + (lane & 7) + ((lane >> 4) & 1) * 8;
            int c = 2 * ks + ((lane >> 3) & 1);
            ldsm_x4(bF, kb + r * 64 + ((c ^ ((r >> 1) & 3)) << 4));
            mma_bf16(acc[nfp * 2],     aF, bF[0], bF[1]);
            mma_bf16(acc[nfp * 2 + 1], aF, bF[2], bF[3]);
        }
    }

    const float* bm = g_bm + (size_t)(w * 4 + h) * 64 * 64;
    #pragma unroll
    for (int hh = 0; hh < 2; hh++) {
        int n = m0 + g + hh * 8;
        const float* bmr = bm + n * 64;
        float vals[16];
        #pragma unroll
        for (int nf = 0; nf < 8; nf++) {
            float2 bv = *(const float2*)(bmr + nf * 8 + tg * 2);
            vals[nf * 2]     = acc[nf][hh * 2]     + bv.x;
            vals[nf * 2 + 1] = acc[nf][hh * 2 + 1] + bv.y;
        }
        float mx = vals[0];
        #pragma unroll
        for (int i = 1; i < 16; i++) mx = fmaxf(mx, vals[i]);
        mx = fmaxf(mx, __shfl_xor_sync(0xffffffffu, mx, 1));
        mx = fmaxf(mx, __shfl_xor_sync(0xffffffffu, mx, 2));
        float sum = 0.f;
        #pragma unroll
        for (int i = 0; i < 16; i++) { vals[i] = __expf(vals[i] - mx); sum += vals[i]; }
        sum += __shfl_xor_sync(0xffffffffu, sum, 1);
        sum += __shfl_xor_sync(0xffffffffu, sum, 2);
        float inv = 1.f / sum;
        #pragma unroll
        for (int nf = 0; nf < 8; nf++) {
            __nv_bfloat162 p;
            p.x = __float2bfloat16_rn(vals[nf * 2] * inv);
            p.y = __float2bfloat16_rn(vals[nf * 2 + 1] * inv);
            *(uint32_t*)(sP + n * 128 + ((nf ^ (n & 7)) << 4) + tg * 4) = *(uint32_t*)&p;
        }
    }
    __syncwarp();

    float acc2[4][4];
    #pragma unroll
    for (int i = 0; i < 4; i++)
        #pragma unroll
        for (int j = 0; j < 4; j++) acc2[i][j] = 0.f;

    #pragma unroll
    for (int ks = 0; ks < 4; ks++) {
        uint32_t aF[4];
        {
            int r = m0 + (lane & 15);
            int c = 2 * ks + (lane >> 4);
            ldsm_x4(aF, pb + r * 128 + ((c ^ (r & 7)) << 4));
        }
        #pragma unroll
        for (int nfp = 0; nfp < 2; nfp++) {
            uint32_t bF[4];
            int rv = ks * 16 + (lane & 7) + ((lane >> 3) & 1) * 8;
            int cv = nfp * 2 + (lane >> 4);
            ldsm_x4_t(bF, vb + rv * 64 + ((cv ^ ((rv >> 1) & 3)) << 4));
            mma_bf16(acc2[nfp * 2],     aF, bF[0], bF[1]);
            mma_bf16(acc2[nfp * 2 + 1], aF, bF[2], bF[3]);
        }
    }

    #pragma unroll
    for (int hh = 0; hh < 2; hh++) {
        int n = m0 + g + hh * 8;
        if (n < 49) {
            __nv_bfloat16* dst = g_xw + ((size_t)bw * NTOK + n) * CCH + h * 32;
            #pragma unroll
            for (int nf = 0; nf < 4; nf++) {
                __nv_bfloat162 o;
                o.x = __float2bfloat16_rn(acc2[nf][hh * 2]);
                o.y = __float2bfloat16_rn(acc2[nf][hh * 2 + 1]);
                *(uint32_t*)(dst + nf * 8 + tg * 2) = *(uint32_t*)&o;
            }
        }
    }
}

#define TILE_B 8192

// ---------------- single-shot K=128 GEMM (dynamic smem) ----------------
// EPI 0: qkv (A=g_xw)   EPI 1: proj (A=g_xw) + scatter + residual + fused LN2 -> g_ln2
// EPI 2: fc1 (A=g_ln2) + GELU
template <int EPI>
__global__ void __launch_bounds__(256, 2)
mma_gemm_k128(const __nv_bfloat16* __restrict__ Wb, const float* __restrict__ bias,
              const float* __restrict__ aux, const float* __restrict__ n2w,
              const float* __restrict__ n2b, int M) {
    extern __shared__ __align__(16) uint8_t smem[];
    const int K = 128;
    const __nv_bfloat16* A = (EPI == 2) ? g_ln2 : g_xw;

    int tid = threadIdx.x, lane = tid & 31, warp = tid >> 5;
    int row0 = blockIdx.x * 128, col0 = blockIdx.y * 128;
    int wm = warp & 1, wn = warp >> 1;
    int g = lane >> 2, tg = lane & 3;

    uint32_t sbase = smem_u32(smem);

    #pragma unroll
    for (int kt = 0; kt < 4; kt++) {
        uint32_t sa = sbase + kt * 2 * TILE_B;
        uint32_t sb = sa + TILE_B;
        #pragma unroll
        for (int hh = 0; hh < 2; hh++) {
            int id = tid + hh * 256;
            int r = id >> 2, c = id & 3;
            uint32_t off = r * 64 + ((c ^ ((r >> 1) & 3)) << 4);
            const __nv_bfloat16* ga = A + (size_t)(row0 + r) * K + kt * 32 + c * 8;
            cp_async16(sa + off, ga, (row0 + r) < M ? 16 : 0);
            const __nv_bfloat16* gb = Wb + (size_t)(col0 + r) * K + kt * 32 + c * 8;
            cp_async16(sb + off, gb, 16);
        }
    }
    asm volatile("cp.async.commit_group;");

    float acc[4][4][4];
    #pragma unroll
    for (int i = 0; i < 4; i++)
        #pragma unroll
        for (int j = 0; j < 4; j++)
            #pragma unroll
            for (int e = 0; e < 4; e++) acc[i][j][e] = 0.f;

    asm volatile("cp.async.wait_group 0;");
    __syncthreads();

    uint32_t aF[2][4][4], bF[2][2][4];
    auto ldstep = [&](int step, int buf) {
        int kt = step >> 1, ks = step & 1;
        uint32_t sa = sbase + kt * 2 * TILE_B;
        uint32_t sb = sa + TILE_B;
        #pragma unroll
        for (int mf = 0; mf < 4; mf++) {
            int r = wm * 64 + mf * 16 + (lane & 15);
            int c = 2 * ks + (lane >> 4);
            ldsm_x4(aF[buf][mf], sa + r * 64 + ((c ^ ((r >> 1) & 3)) << 4));
        }
        #pragma unroll
        for (int nfp = 0; nfp < 2; nfp++) {
            int r = wn * 32 + nfp * 16 + (lane & 7) + ((lane >> 4) & 1) * 8;
            int c = 2 * ks + ((lane >> 3) & 1);
            ldsm_x4(bF[buf][nfp], sb + r * 64 + ((c ^ ((r >> 1) & 3)) << 4));
        }
    };
    ldstep(0, 0);
    #pragma unroll
    for (int s = 0; s < 8; s++) {
        int cur = s & 1;
        if (s < 7) ldstep(s + 1, cur ^ 1);
        #pragma unroll
        for (int mf = 0; mf < 4; mf++)
            #pragma unroll
            for (int nf = 0; nf < 4; nf++)
                mma_bf16(acc[mf][nf], aF[cur][mf],
                         bF[cur][nf >> 1][(nf & 1) * 2], bF[cur][nf >> 1][(nf & 1) * 2 + 1]);
    }

    if (EPI == 1) {
        // stage fp32 outputs in smem for fused LN2 (writes g_x2 + g_ln2, NOT A)
        __syncthreads();
        float* sC = (float*)smem;
        #pragma unroll
        for (int mf = 0; mf < 4; mf++) {
            #pragma unroll
            for (int hh = 0; hh < 2; hh++) {
                int rl = wm * 64 + mf * 16 + g + hh * 8;
                int r = row0 + rl;
                if (r >= M) continue;
                int bw = r / 49, tok = r - bw * 49;
                int bb = bw / 49, wi = bw - bb * 49;
                int R  = (wi / 7) * 7 + tok / 7;
                int Cl = (wi % 7) * 7 + tok % 7;
                int rr = R + 3;  if (rr >= 49) rr -= 49;
                int cc = Cl + 3; if (cc >= 49) cc -= 49;
                size_t dest = ((size_t)bb * 2401 + rr * 49 + cc) * 128;
                #pragma unroll
                for (int nf = 0; nf < 4; nf++)
                    #pragma unroll
                    for (int e = 0; e < 2; e++) {
                        int n = wn * 32 + nf * 8 + tg * 2 + e;
                        float v = acc[mf][nf][hh * 2 + e] + bias[n] + aux[dest + n];
                        g_x2[dest + n] = v;
                        sC[rl * 129 + n] = v;
                    }
            }
        }
        __syncthreads();
        int rl = tid >> 1, half = tid & 1;
        int r = row0 + rl;
        if (r < M) {
            float s = 0.f, s2 = 0.f;
            #pragma unroll 8
            for (int c = 0; c < 64; c++) {
                float v = sC[rl * 129 + half * 64 + c];
                s += v; s2 += v * v;
            }
            s  += __shfl_xor_sync(0xffffffffu, s,  1);
            s2 += __shfl_xor_sync(0xffffffffu, s2, 1);
            float mean = s * (1.f / 128.f);
            float var  = s2 * (1.f / 128.f) - mean * mean;
            float rstd = rsqrtf(var + 1e-5f);
            int bw = r / 49, tok = r - bw * 49;
            int bb = bw / 49, wi = bw - bb * 49;
            int R  = (wi / 7) * 7 + tok / 7;
            int Cl = (wi % 7) * 7 + tok % 7;
            int rr = R + 3;  if (rr >= 49) rr -= 49;
            int cc = Cl + 3; if (cc >= 49) cc -= 49;
            size_t dest = ((size_t)bb * 2401 + rr * 49 + cc) * 128;
            #pragma unroll 8
            for (int c = 0; c < 64; c++) {
                int ch = half * 64 + c;
                float v = sC[rl * 129 + ch];
                g_ln2[dest + ch] = __float2bfloat16_rn((v - mean) * rstd * n2w[ch] + n2b[ch]);
            }
        }
    } else {
        #pragma unroll
        for (int mf = 0; mf < 4; mf++) {
            #pragma unroll
            for (int hh = 0; hh < 2; hh++) {
                int r = row0 + wm * 64 + mf * 16 + g + hh * 8;
                if (r >= M) continue;
                #pragma unroll
                for (int nf = 0; nf < 4; nf++)
                    #pragma unroll
                    for (int e = 0; e < 2; e++) {
                        int n = col0 + wn * 32 + nf * 8 + tg * 2 + e;
                        float v = acc[mf][nf][hh * 2 + e] + bias[n];
                        if (EPI == 0) {
                            if (n < 128) v *= QSCALE;
                            g_big[(size_t)r * 384 + n] = __float2bfloat16_rn(v);
                        } else {
                            v = 0.5f * v * (1.f + erff(v * 0.70710678118654752f));
                            g_big[(size_t)r * 512 + n] = __float2bfloat16_rn(v);
                        }
                    }
            }
        }
    }
}

// ---------------- pipelined GEMM for fc2 (K=512) ----------------
#define BK 32
#define STAGES 3
__global__ void __launch_bounds__(256, 2)
mma_gemm_fc2(const __nv_bfloat16* __restrict__ Wb, const float* __restrict__ bias,
             float* __restrict__ extC, int M, int K) {
    __shared__ __align__(16) uint8_t smem[STAGES * 2 * TILE_B];
    const __nv_bfloat16* A = g_big;

    int tid = threadIdx.x, lane = tid & 31, warp = tid >> 5;
    int row0 = blockIdx.x * 128, col0 = 0;
    int wm = warp & 1, wn = warp >> 1;
    int g = lane >> 2, tg = lane & 3;

    float acc[4][4][4];
    #pragma unroll
    for (int i = 0; i < 4; i++)
        #pragma unroll
        for (int j = 0; j < 4; j++)
            #pragma unroll
            for (int e = 0; e < 4; e++) acc[i][j][e] = 0.f;

    uint32_t sbase = smem_u32(smem);
    const int nkt = K / BK;

    auto load_tile = [&](int kt, int st) {
        uint32_t sa = sbase + st * 2 * TILE_B;
        uint32_t sb = sa + TILE_B;
        #pragma unroll
        for (int h = 0; h < 2; h++) {
            int id = tid + h * 256;
            int r = id >> 2, c = id & 3;
            uint32_t off = r * 64 + ((c ^ ((r >> 1) & 3)) << 4);
            const __nv_bfloat16* ga = A + (size_t)(row0 + r) * K + kt * BK + c * 8;
            cp_async16(sa + off, ga, (row0 + r) < M ? 16 : 0);
            const __nv_bfloat16* gb = Wb + (size_t)(col0 + r) * K + kt * BK + c * 8;
            cp_async16(sb + off, gb, 16);
        }
        asm volatile("cp.async.commit_group;");
    };

    load_tile(0, 0);
    load_tile(1, 1);

    for (int kt = 0; kt < nkt; kt++) {
        if (kt < nkt - 1) asm volatile("cp.async.wait_group 1;");
        else              asm volatile("cp.async.wait_group 0;");
        __syncthreads();
        if (kt + 2 < nkt) load_tile(kt + 2, (kt + 2) % STAGES);

        int st = kt % STAGES;
        uint32_t sa = sbase + st * 2 * TILE_B;
        uint32_t sb = sa + TILE_B;
        #pragma unroll
        for (int ks = 0; ks < 2; ks++) {
            uint32_t aF[4][4], bF[2][4];
            #pragma unroll
            for (int mf = 0; mf < 4; mf++) {
                int r = wm * 64 + mf * 16 + (lane & 15);
                int c = 2 * ks + (lane >> 4);
                ldsm_x4(aF[mf], sa + r * 64 + ((c ^ ((r >> 1) & 3)) << 4));
            }
            #pragma unroll
            for (int nfp = 0; nfp < 2; nfp++) {
                int r = wn * 32 + nfp * 16 + (lane & 7) + ((lane >> 4) & 1) * 8;
                int c = 2 * ks + ((lane >> 3) & 1);
                ldsm_x4(bF[nfp], sb + r * 64 + ((c ^ ((r >> 1) & 3)) << 4));
            }
            #pragma unroll
            for (int mf = 0; mf < 4; mf++)
                #pragma unroll
                for (int nf = 0; nf < 4; nf++)
                    mma_bf16(acc[mf][nf], aF[mf],
                             bF[nf >> 1][(nf & 1) * 2], bF[nf >> 1][(nf & 1) * 2 + 1]);
        }
    }

    #pragma unroll
    for (int mf = 0; mf < 4; mf++) {
        #pragma unroll
        for (int h = 0; h < 2; h++) {
            int r = row0 + wm * 64 + mf * 16 + g + h * 8;
            if (r >= M) continue;
            #pragma unroll
            for (int nf = 0; nf < 4; nf++)
                #pragma unroll
                for (int e = 0; e < 2; e++) {
                    int n = wn * 32 + nf * 8 + tg * 2 + e;
                    float v = acc[mf][nf][h * 2 + e] + bias[n];
                    extC[(size_t)r * 128 + n] = g_x2[(size_t)r * 128 + n] + v;
                }
        }
    }
}

// ---------------- launch ----------------
extern "C" void kernel_launch(void* const* d_in, const int* in_sizes, int n_in,
                              void* d_out, int out_size) {
    const float* x      = (const float*)d_in[0];
    const float* n1w    = (const float*)d_in[1];
    const float* n1b    = (const float*)d_in[2];
    const float* qkv_w  = (const float*)d_in[3];
    const float* qkv_b  = (const float*)d_in[4];
    const float* proj_w = (const float*)d_in[5];
    const float* proj_b = (const float*)d_in[6];
    const float* rpb    = (const float*)d_in[7];
    const float* n2w    = (const float*)d_in[8];
    const float* n2b    = (const float*)d_in[9];
    const float* fc1_w  = (const float*)d_in[10];
    const float* fc1_b  = (const float*)d_in[11];
    const float* fc2_w  = (const float*)d_in[12];
    const float* fc2_b  = (const float*)d_in[13];
    float* out = (float*)d_out;

    const int M = MROWS;
    const int gm = (M + 127) / 128;   // 901

    static bool attr_set = false;
    if (!attr_set) {
        cudaFuncSetAttribute(mma_gemm_k128<0>, cudaFuncAttributeMaxDynamicSharedMemorySize, 65536);
        cudaFuncSetAttribute(mma_gemm_k128<1>, cudaFuncAttributeMaxDynamicSharedMemorySize, 66048);
        cudaFuncSetAttribute(mma_gemm_k128<2>, cudaFuncAttributeMaxDynamicSharedMemorySize, 65536);
        attr_set = true;
    }

    cvt_weights<<<256, 256>>>(qkv_w, proj_w, fc1_w, fc2_w);
    build_bm<<<dim3(49, 4), 256>>>(rpb);
    ln1_gather_kernel<<<M, 128>>>(x, n1w, n1b);

    __nv_bfloat16* wbase;
    cudaGetSymbolAddress((void**)&wbase, g_wts);

    mma_gemm_k128<0><<<dim3(gm, 3), 256, 65536>>>(wbase + WOFF_QKV, qkv_b, nullptr, nullptr, nullptr, M);
    attn_kernel<<<dim3(BN * NWIN, 4), 128>>>();
    mma_gemm_k128<1><<<dim3(gm, 1), 256, 66048>>>(wbase + WOFF_PROJ, proj_b, x, n2w, n2b, M);
    mma_gemm_k128<2><<<dim3(gm, 4), 256, 65536>>>(wbase + WOFF_FC1, fc1_b, nullptr, nullptr, nullptr, M);
    mma_gemm_fc2<<<dim3(gm, 1), 256>>>(wbase + WOFF_FC2, fc2_b, out, M, 512);
}

// round 8
// speedup vs baseline: 1.0767x; 1.0767x over previous
#include <cuda_runtime.h>
#include <cuda_bf16.h>
#include <math.h>
#include <stdint.h>

// ---------------- problem constants ----------------
#define BN    48
#define CCH   128
#define NWIN  49
#define NTOK  49
#define MROWS (BN*NWIN*NTOK)   // 115248
#define NMT   901              // ceil(MROWS/128)
#define HID   512
#define QSCALE 0.17677669529663687f

// ---------------- scratch (device globals) ----------------
__device__ __nv_bfloat16 g_xw [(size_t)MROWS*CCH];   // LN1 out -> attn out -> LN2 out
__device__ __nv_bfloat16 g_big[(size_t)MROWS*HID];   // qkv (stride 384) then hidden (stride 512)
__device__ float         g_x2 [(size_t)MROWS*CCH];   // fp32 residual (x layout)
__device__ __nv_bfloat16 g_wts[196608];
__device__ float         g_bm [49*4*64*64];
#define WOFF_QKV 0
#define WOFF_PROJ 49152
#define WOFF_FC1  65536
#define WOFF_FC2  131072

// ---------------- asm helpers ----------------
__device__ __forceinline__ uint32_t smem_u32(const void* p) {
    return (uint32_t)__cvta_generic_to_shared(p);
}
__device__ __forceinline__ void cp_async16(uint32_t dst, const void* src, int sz) {
    asm volatile("cp.async.cg.shared.global [%0], [%1], 16, %2;"
                 :: "r"(dst), "l"(src), "r"(sz));
}
__device__ __forceinline__ void ldsm_x4(uint32_t r[4], uint32_t addr) {
    asm volatile("ldmatrix.sync.aligned.m8n8.x4.shared.b16 {%0,%1,%2,%3}, [%4];"
                 : "=r"(r[0]), "=r"(r[1]), "=r"(r[2]), "=r"(r[3]) : "r"(addr));
}
__device__ __forceinline__ void ldsm_x4_t(uint32_t r[4], uint32_t addr) {
    asm volatile("ldmatrix.sync.aligned.m8n8.x4.trans.shared.b16 {%0,%1,%2,%3}, [%4];"
                 : "=r"(r[0]), "=r"(r[1]), "=r"(r[2]), "=r"(r[3]) : "r"(addr));
}
__device__ __forceinline__ void mma_bf16(float c[4], const uint32_t a[4],
                                         uint32_t b0, uint32_t b1) {
    asm volatile("mma.sync.aligned.m16n8k16.row.col.f32.bf16.bf16.f32 "
                 "{%0,%1,%2,%3}, {%4,%5,%6,%7}, {%8,%9}, {%0,%1,%2,%3};"
                 : "+f"(c[0]), "+f"(c[1]), "+f"(c[2]), "+f"(c[3])
                 : "r"(a[0]), "r"(a[1]), "r"(a[2]), "r"(a[3]), "r"(b0), "r"(b1));
}

// ---------------- weight convert ----------------
__global__ void cvt_weights(const float* __restrict__ qkv_w, const float* __restrict__ proj_w,
                            const float* __restrict__ fc1_w, const float* __restrict__ fc2_w) {
    int i = blockIdx.x * 256 + threadIdx.x;
    if (i < 49152)       g_wts[WOFF_QKV  + i] = __float2bfloat16_rn(qkv_w[i]);
    if (i < 16384)       g_wts[WOFF_PROJ + i] = __float2bfloat16_rn(proj_w[i]);
    if (i < 65536) {     g_wts[WOFF_FC1  + i] = __float2bfloat16_rn(fc1_w[i]);
                         g_wts[WOFF_FC2  + i] = __float2bfloat16_rn(fc2_w[i]); }
}

// ---------------- bias+mask table ----------------
__device__ __forceinline__ int regn(int wq, int iq) {
    return (wq < 6) ? 0 : ((iq < 4) ? 1 : 2);
}
__global__ void build_bm(const float* __restrict__ rpb) {
    int w = blockIdx.x, h = blockIdx.y;
    int wh = w / 7, ww = w % 7;
    for (int e = threadIdx.x; e < 64 * 64; e += 256) {
        int n = e >> 6, m = e & 63;
        float v;
        if (n < 49 && m < 49) {
            int i1 = n / 7, j1 = n % 7, i2 = m / 7, j2 = m % 7;
            v = rpb[((i1 - i2 + 6) * 13 + (j1 - j2 + 6)) * 4 + h];
            int mwW = regn(wh, i2) * 3 + regn(ww, j2);
            int mwN = regn(i1, i2) * 3 + regn(j1, j2);
            if (mwW != mwN) v -= 100.f;
        } else {
            v = -1e9f;
        }
        g_bm[((size_t)(w * 4 + h) * 64 + n) * 64 + m] = v;
    }
}

// ---------------- LN1 + shift + window gather ----------------
__global__ void ln1_gather_kernel(const float* __restrict__ x,
                                  const float* __restrict__ w,
                                  const float* __restrict__ b) {
    int t = blockIdx.x, c = threadIdx.x;
    int bw = t / NTOK, n = t - bw * NTOK;
    int bb = bw / NWIN, wi = bw - bb * NWIN;
    int R  = (wi / 7) * 7 + n / 7;
    int Cl = (wi % 7) * 7 + n % 7;
    int sr = R + 3;  if (sr >= 49) sr -= 49;
    int sc = Cl + 3; if (sc >= 49) sc -= 49;
    float v = x[((size_t)bb * 2401 + sr * 49 + sc) * CCH + c];
    float s = v, s2 = v * v;
    #pragma unroll
    for (int o = 16; o > 0; o >>= 1) {
        s  += __shfl_xor_sync(0xffffffffu, s,  o);
        s2 += __shfl_xor_sync(0xffffffffu, s2, o);
    }
    __shared__ float red[8];
    int wid = c >> 5, lane = c & 31;
    if (lane == 0) { red[wid] = s; red[4 + wid] = s2; }
    __syncthreads();
    float ts  = red[0] + red[1] + red[2] + red[3];
    float ts2 = red[4] + red[5] + red[6] + red[7];
    float mean = ts * (1.f / 128.f);
    float var  = ts2 * (1.f / 128.f) - mean * mean;
    float rstd = rsqrtf(var + 1e-5f);
    g_xw[(size_t)t * CCH + c] = __float2bfloat16_rn((v - mean) * rstd * w[c] + b[c]);
}

// ---------------- LN2 ----------------
__global__ void ln2_kernel(const float* __restrict__ w,
                           const float* __restrict__ b) {
    int t = blockIdx.x, c = threadIdx.x;
    float v = g_x2[(size_t)t * CCH + c];
    float s = v, s2 = v * v;
    #pragma unroll
    for (int o = 16; o > 0; o >>= 1) {
        s  += __shfl_xor_sync(0xffffffffu, s,  o);
        s2 += __shfl_xor_sync(0xffffffffu, s2, o);
    }
    __shared__ float red[8];
    int wid = c >> 5, lane = c & 31;
    if (lane == 0) { red[wid] = s; red[4 + wid] = s2; }
    __syncthreads();
    float ts  = red[0] + red[1] + red[2] + red[3];
    float ts2 = red[4] + red[5] + red[6] + red[7];
    float mean = ts * (1.f / 128.f);
    float var  = ts2 * (1.f / 128.f) - mean * mean;
    float rstd = rsqrtf(var + 1e-5f);
    g_xw[(size_t)t * CCH + c] = __float2bfloat16_rn((v - mean) * rstd * w[c] + b[c]);
}

// ---------------- tensor-core attention (unchanged, passing) ----------------
__global__ void __launch_bounds__(128) attn_kernel() {
    int bw = blockIdx.x, h = blockIdx.y;
    int w  = bw % NWIN;
    int tid = threadIdx.x, lane = tid & 31, warp = tid >> 5;

    __shared__ __align__(16) uint8_t sQ[64 * 64];
    __shared__ __align__(16) uint8_t sK[64 * 64];
    __shared__ __align__(16) uint8_t sV[64 * 64];
    __shared__ __align__(16) uint8_t sP[64 * 128];

    uint32_t qb = smem_u32(sQ), kb = smem_u32(sK);
    uint32_t vb = smem_u32(sV), pb = smem_u32(sP);

    const __nv_bfloat16* base = g_big + (size_t)bw * NTOK * 384;
    for (int id = tid; id < 768; id += 128) {
        int op = id >> 8;
        int r  = (id >> 2) & 63;
        int c  = id & 3;
        uint32_t sb = (op == 0) ? qb : (op == 1) ? kb : vb;
        uint32_t dst = sb + r * 64 + ((c ^ ((r >> 1) & 3)) << 4);
        const __nv_bfloat16* src = base + (r < 49 ? r : 0) * 384 + op * 128 + h * 32 + c * 8;
        cp_async16(dst, src, r < 49 ? 16 : 0);
    }
    asm volatile("cp.async.commit_group;");
    asm volatile("cp.async.wait_group 0;");
    __syncthreads();

    int g = lane >> 2, tg = lane & 3;
    int m0 = warp * 16;

    float acc[8][4];
    #pragma unroll
    for (int i = 0; i < 8; i++)
        #pragma unroll
        for (int j = 0; j < 4; j++) acc[i][j] = 0.f;

    #pragma unroll
    for (int ks = 0; ks < 2; ks++) {
        uint32_t aF[4];
        {
            int r = m0 + (lane & 15);
            int c = 2 * ks + (lane >> 4);
            ldsm_x4(aF, qb + r * 64 + ((c ^ ((r >> 1) & 3)) << 4));
        }
        #pragma unroll
        for (int nfp = 0; nfp < 4; nfp++) {
            uint32_t bF[4];
            int r = nfp * 16 + (lane & 7) + ((lane >> 4) & 1) * 8;
            int c = 2 * ks + ((lane >> 3) & 1);
            ldsm_x4(bF, kb + r * 64 + ((c ^ ((r >> 1) & 3)) << 4));
            mma_bf16(acc[nfp * 2],     aF, bF[0], bF[1]);
            mma_bf16(acc[nfp * 2 + 1], aF, bF[2], bF[3]);
        }
    }

    const float* bm = g_bm + (size_t)(w * 4 + h) * 64 * 64;
    #pragma unroll
    for (int hh = 0; hh < 2; hh++) {
        int n = m0 + g + hh * 8;
        const float* bmr = bm + n * 64;
        float vals[16];
        #pragma unroll
        for (int nf = 0; nf < 8; nf++) {
            float2 bv = *(const float2*)(bmr + nf * 8 + tg * 2);
            vals[nf * 2]     = acc[nf][hh * 2]     + bv.x;
            vals[nf * 2 + 1] = acc[nf][hh * 2 + 1] + bv.y;
        }
        float mx = vals[0];
        #pragma unroll
        for (int i = 1; i < 16; i++) mx = fmaxf(mx, vals[i]);
        mx = fmaxf(mx, __shfl_xor_sync(0xffffffffu, mx, 1));
        mx = fmaxf(mx, __shfl_xor_sync(0xffffffffu, mx, 2));
        float sum = 0.f;
        #pragma unroll
        for (int i = 0; i < 16; i++) { vals[i] = __expf(vals[i] - mx); sum += vals[i]; }
        sum += __shfl_xor_sync(0xffffffffu, sum, 1);
        sum += __shfl_xor_sync(0xffffffffu, sum, 2);
        float inv = 1.f / sum;
        #pragma unroll
        for (int nf = 0; nf < 8; nf++) {
            __nv_bfloat162 p;
            p.x = __float2bfloat16_rn(vals[nf * 2] * inv);
            p.y = __float2bfloat16_rn(vals[nf * 2 + 1] * inv);
            *(uint32_t*)(sP + n * 128 + ((nf ^ (n & 7)) << 4) + tg * 4) = *(uint32_t*)&p;
        }
    }
    __syncwarp();

    float acc2[4][4];
    #pragma unroll
    for (int i = 0; i < 4; i++)
        #pragma unroll
        for (int j = 0; j < 4; j++) acc2[i][j] = 0.f;

    #pragma unroll
    for (int ks = 0; ks < 4; ks++) {
        uint32_t aF[4];
        {
            int r = m0 + (lane & 15);
            int c = 2 * ks + (lane >> 4);
            ldsm_x4(aF, pb + r * 128 + ((c ^ (r & 7)) << 4));
        }
        #pragma unroll
        for (int nfp = 0; nfp < 2; nfp++) {
            uint32_t bF[4];
            int rv = ks * 16 + (lane & 7) + ((lane >> 3) & 1) * 8;
            int cv = nfp * 2 + (lane >> 4);
            ldsm_x4_t(bF, vb + rv * 64 + ((cv ^ ((rv >> 1) & 3)) << 4));
            mma_bf16(acc2[nfp * 2],     aF, bF[0], bF[1]);
            mma_bf16(acc2[nfp * 2 + 1], aF, bF[2], bF[3]);
        }
    }

    #pragma unroll
    for (int hh = 0; hh < 2; hh++) {
        int n = m0 + g + hh * 8;
        if (n < 49) {
            __nv_bfloat16* dst = g_xw + ((size_t)bw * NTOK + n) * CCH + h * 32;
            #pragma unroll
            for (int nf = 0; nf < 4; nf++) {
                __nv_bfloat162 o;
                o.x = __float2bfloat16_rn(acc2[nf][hh * 2]);
                o.y = __float2bfloat16_rn(acc2[nf][hh * 2 + 1]);
                *(uint32_t*)(dst + nf * 8 + tg * 2) = *(uint32_t*)&o;
            }
        }
    }
}

#define TILE_B 8192

// ---------------- persistent K=128 GEMM: W resident in smem, M-tile streaming ----
// smem: [ W 32KB | A stage0 32KB | A stage1 32KB ]  (dynamic, 96KB)
// EPI 0: qkv (out g_big s384, q scaled)  EPI 1: proj (scatter+residual -> g_x2)
// EPI 2: fc1 (gelu -> g_big s512)
template <int EPI>
__global__ void __launch_bounds__(256, 2)
pgemm(const __nv_bfloat16* __restrict__ Wb, const float* __restrict__ bias,
      const float* __restrict__ aux, int M) {
    extern __shared__ __align__(16) uint8_t smem[];
    const __nv_bfloat16* A = g_xw;

    int tid = threadIdx.x, lane = tid & 31, warp = tid >> 5;
    int col0 = blockIdx.y * 128;
    int wm = warp & 1, wn = warp >> 1;
    int g = lane >> 2, tg = lane & 3;

    uint32_t sbase = smem_u32(smem);
    uint32_t sW = sbase;
    uint32_t sA0 = sbase + 32768;

    // per-thread load coords (same for every 16B-chunk burst)
    int lr = tid >> 2;                 // rows handled: lr and lr+64
    int lc = tid & 3;

    // ---- load W (all 4 k-chunks) once ----
    #pragma unroll
    for (int kt = 0; kt < 4; kt++) {
        #pragma unroll
        for (int hh = 0; hh < 2; hh++) {
            int r = lr + hh * 64;
            uint32_t off = r * 64 + ((lc ^ ((r >> 1) & 3)) << 4);
            const __nv_bfloat16* gp = Wb + (size_t)(col0 + r) * 128 + kt * 32 + lc * 8;
            cp_async16(sW + kt * TILE_B + off, gp, 16);
        }
    }
    asm volatile("cp.async.commit_group;");

    // ---- preload per-thread bias (cols fixed for CTA lifetime) ----
    float bias_r[8];
    float qsc[8];
    #pragma unroll
    for (int nf = 0; nf < 4; nf++)
        #pragma unroll
        for (int e = 0; e < 2; e++) {
            int n = col0 + wn * 32 + nf * 8 + tg * 2 + e;
            bias_r[nf * 2 + e] = bias[n];
            qsc[nf * 2 + e] = (EPI == 0 && n < 128) ? QSCALE : 1.f;
        }

    auto load_A = [&](int mt, int st) {
        uint32_t base = sA0 + st * 32768;
        int row0 = mt * 128;
        #pragma unroll
        for (int kt = 0; kt < 4; kt++) {
            #pragma unroll
            for (int hh = 0; hh < 2; hh++) {
                int r = lr + hh * 64;
                uint32_t off = r * 64 + ((lc ^ ((r >> 1) & 3)) << 4);
                const __nv_bfloat16* gp = A + (size_t)(row0 + r) * 128 + kt * 32 + lc * 8;
                cp_async16(base + kt * TILE_B + off, gp, (row0 + r) < M ? 16 : 0);
            }
        }
        asm volatile("cp.async.commit_group;");
    };

    int mt = blockIdx.x;
    if (mt < NMT) load_A(mt, 0);

    int i = 0;
    for (; mt < NMT; i++) {
        int nxt = mt + gridDim.x;
        int st = i & 1;
        if (nxt < NMT) load_A(nxt, st ^ 1);

        if (nxt < NMT) asm volatile("cp.async.wait_group 1;");
        else           asm volatile("cp.async.wait_group 0;");
        __syncthreads();

        float acc[4][4][4];
        #pragma unroll
        for (int a = 0; a < 4; a++)
            #pragma unroll
            for (int b = 0; b < 4; b++)
                #pragma unroll
                for (int e = 0; e < 4; e++) acc[a][b][e] = 0.f;

        uint32_t aBase = sA0 + st * 32768;
        #pragma unroll
        for (int kt = 0; kt < 4; kt++) {
            uint32_t sa = aBase + kt * TILE_B;
            uint32_t sb = sW + kt * TILE_B;
            #pragma unroll
            for (int ks = 0; ks < 2; ks++) {
                uint32_t aF[4][4], bF[2][4];
                #pragma unroll
                for (int mf = 0; mf < 4; mf++) {
                    int r = wm * 64 + mf * 16 + (lane & 15);
                    int c = 2 * ks + (lane >> 4);
                    ldsm_x4(aF[mf], sa + r * 64 + ((c ^ ((r >> 1) & 3)) << 4));
                }
                #pragma unroll
                for (int nfp = 0; nfp < 2; nfp++) {
                    int r = wn * 32 + nfp * 16 + (lane & 7) + ((lane >> 4) & 1) * 8;
                    int c = 2 * ks + ((lane >> 3) & 1);
                    ldsm_x4(bF[nfp], sb + r * 64 + ((c ^ ((r >> 1) & 3)) << 4));
                }
                #pragma unroll
                for (int mf = 0; mf < 4; mf++)
                    #pragma unroll
                    for (int nf = 0; nf < 4; nf++)
                        mma_bf16(acc[mf][nf], aF[mf],
                                 bF[nf >> 1][(nf & 1) * 2], bF[nf >> 1][(nf & 1) * 2 + 1]);
            }
        }
        __syncthreads();   // all warps done reading stage st before it is reloaded

        // ---- epilogue for tile mt ----
        int row0 = mt * 128;
        #pragma unroll
        for (int mf = 0; mf < 4; mf++) {
            #pragma unroll
            for (int hh = 0; hh < 2; hh++) {
                int r = row0 + wm * 64 + mf * 16 + g + hh * 8;
                if (r >= M) continue;
                size_t dest = 0;
                if (EPI == 1) {
                    int bw = r / 49, tok = r - bw * 49;
                    int bb = bw / 49, wi = bw - bb * 49;
                    int R  = (wi / 7) * 7 + tok / 7;
                    int Cl = (wi % 7) * 7 + tok % 7;
                    int rr = R + 3;  if (rr >= 49) rr -= 49;
                    int cc = Cl + 3; if (cc >= 49) cc -= 49;
                    dest = ((size_t)bb * 2401 + rr * 49 + cc) * 128;
                }
                #pragma unroll
                for (int nf = 0; nf < 4; nf++) {
                    #pragma unroll
                    for (int e = 0; e < 2; e++) {
                        int n = col0 + wn * 32 + nf * 8 + tg * 2 + e;
                        float v = acc[mf][nf][hh * 2 + e] + bias_r[nf * 2 + e];
                        if (EPI == 0) {
                            v *= qsc[nf * 2 + e];
                            g_big[(size_t)r * 384 + n] = __float2bfloat16_rn(v);
                        } else if (EPI == 1) {
                            g_x2[dest + n] = aux[dest + n] + v;
                        } else {
                            v = 0.5f * v * (1.f + erff(v * 0.70710678118654752f));
                            g_big[(size_t)r * 512 + n] = __float2bfloat16_rn(v);
                        }
                    }
                }
            }
        }
        mt = nxt;
    }
}

// ---------------- pipelined GEMM for fc2 (K=512) ----------------
#define BK 32
#define STAGES 3
__global__ void __launch_bounds__(256, 2)
mma_gemm_fc2(const __nv_bfloat16* __restrict__ Wb, const float* __restrict__ bias,
             float* __restrict__ extC, int M, int K) {
    __shared__ __align__(16) uint8_t smem[STAGES * 2 * TILE_B];
    const __nv_bfloat16* A = g_big;

    int tid = threadIdx.x, lane = tid & 31, warp = tid >> 5;
    int row0 = blockIdx.x * 128;
    int wm = warp & 1, wn = warp >> 1;
    int g = lane >> 2, tg = lane & 3;

    float acc[4][4][4];
    #pragma unroll
    for (int i = 0; i < 4; i++)
        #pragma unroll
        for (int j = 0; j < 4; j++)
            #pragma unroll
            for (int e = 0; e < 4; e++) acc[i][j][e] = 0.f;

    uint32_t sbase = smem_u32(smem);
    const int nkt = K / BK;

    auto load_tile = [&](int kt, int st) {
        uint32_t sa = sbase + st * 2 * TILE_B;
        uint32_t sb = sa + TILE_B;
        #pragma unroll
        for (int h = 0; h < 2; h++) {
            int id = tid + h * 256;
            int r = id >> 2, c = id & 3;
            uint32_t off = r * 64 + ((c ^ ((r >> 1) & 3)) << 4);
            const __nv_bfloat16* ga = A + (size_t)(row0 + r) * K + kt * BK + c * 8;
            cp_async16(sa + off, ga, (row0 + r) < M ? 16 : 0);
            const __nv_bfloat16* gb = Wb + (size_t)r * K + kt * BK + c * 8;
            cp_async16(sb + off, gb, 16);
        }
        asm volatile("cp.async.commit_group;");
    };

    load_tile(0, 0);
    load_tile(1, 1);

    for (int kt = 0; kt < nkt; kt++) {
        if (kt < nkt - 1) asm volatile("cp.async.wait_group 1;");
        else              asm volatile("cp.async.wait_group 0;");
        __syncthreads();
        if (kt + 2 < nkt) load_tile(kt + 2, (kt + 2) % STAGES);

        int st = kt % STAGES;
        uint32_t sa = sbase + st * 2 * TILE_B;
        uint32_t sb = sa + TILE_B;
        #pragma unroll
        for (int ks = 0; ks < 2; ks++) {
            uint32_t aF[4][4], bF[2][4];
            #pragma unroll
            for (int mf = 0; mf < 4; mf++) {
                int r = wm * 64 + mf * 16 + (lane & 15);
                int c = 2 * ks + (lane >> 4);
                ldsm_x4(aF[mf], sa + r * 64 + ((c ^ ((r >> 1) & 3)) << 4));
            }
            #pragma unroll
            for (int nfp = 0; nfp < 2; nfp++) {
                int r = wn * 32 + nfp * 16 + (lane & 7) + ((lane >> 4) & 1) * 8;
                int c = 2 * ks + ((lane >> 3) & 1);
                ldsm_x4(bF[nfp], sb + r * 64 + ((c ^ ((r >> 1) & 3)) << 4));
            }
            #pragma unroll
            for (int mf = 0; mf < 4; mf++)
                #pragma unroll
                for (int nf = 0; nf < 4; nf++)
                    mma_bf16(acc[mf][nf], aF[mf],
                             bF[nf >> 1][(nf & 1) * 2], bF[nf >> 1][(nf & 1) * 2 + 1]);
        }
    }

    #pragma unroll
    for (int mf = 0; mf < 4; mf++) {
        #pragma unroll
        for (int h = 0; h < 2; h++) {
            int r = row0 + wm * 64 + mf * 16 + g + h * 8;
            if (r >= M) continue;
            #pragma unroll
            for (int nf = 0; nf < 4; nf++)
                #pragma unroll
                for (int e = 0; e < 2; e++) {
                    int n = wn * 32 + nf * 8 + tg * 2 + e;
                    float v = acc[mf][nf][h * 2 + e] + bias[n];
                    extC[(size_t)r * 128 + n] = g_x2[(size_t)r * 128 + n] + v;
                }
        }
    }
}

// ---------------- launch ----------------
extern "C" void kernel_launch(void* const* d_in, const int* in_sizes, int n_in,
                              void* d_out, int out_size) {
    const float* x      = (const float*)d_in[0];
    const float* n1w    = (const float*)d_in[1];
    const float* n1b    = (const float*)d_in[2];
    const float* qkv_w  = (const float*)d_in[3];
    const float* qkv_b  = (const float*)d_in[4];
    const float* proj_w = (const float*)d_in[5];
    const float* proj_b = (const float*)d_in[6];
    const float* rpb    = (const float*)d_in[7];
    const float* n2w    = (const float*)d_in[8];
    const float* n2b    = (const float*)d_in[9];
    const float* fc1_w  = (const float*)d_in[10];
    const float* fc1_b  = (const float*)d_in[11];
    const float* fc2_w  = (const float*)d_in[12];
    const float* fc2_b  = (const float*)d_in[13];
    float* out = (float*)d_out;

    const int M = MROWS;
    const int gm = (M + 127) / 128;   // 901
    const int PSMEM = 3 * 32768;      // 96KB: W + 2 A stages

    cudaFuncSetAttribute(pgemm<0>, cudaFuncAttributeMaxDynamicSharedMemorySize, PSMEM);
    cudaFuncSetAttribute(pgemm<1>, cudaFuncAttributeMaxDynamicSharedMemorySize, PSMEM);
    cudaFuncSetAttribute(pgemm<2>, cudaFuncAttributeMaxDynamicSharedMemorySize, PSMEM);

    cvt_weights<<<256, 256>>>(qkv_w, proj_w, fc1_w, fc2_w);
    build_bm<<<dim3(49, 4), 256>>>(rpb);
    ln1_gather_kernel<<<M, 128>>>(x, n1w, n1b);

    __nv_bfloat16* wbase;
    cudaGetSymbolAddress((void**)&wbase, g_wts);

    pgemm<0><<<dim3(96, 3), 256, PSMEM>>>(wbase + WOFF_QKV, qkv_b, nullptr, M);
    attn_kernel<<<dim3(BN * NWIN, 4), 128>>>();
    pgemm<1><<<dim3(288, 1), 256, PSMEM>>>(wbase + WOFF_PROJ, proj_b, x, M);
    ln2_kernel<<<M, 128>>>(n2w, n2b);
    pgemm<2><<<dim3(74, 4), 256, PSMEM>>>(wbase + WOFF_FC1, fc1_b, nullptr, M);
    mma_gemm_fc2<<<dim3(gm, 1), 256>>>(wbase + WOFF_FC2, fc2_b, out, M, 512);
}

// round 9
// speedup vs baseline: 1.0965x; 1.0184x over previous
#include <cuda_runtime.h>
#include <cuda_bf16.h>
#include <math.h>
#include <stdint.h>

// ---------------- problem constants ----------------
#define BN    48
#define CCH   128
#define NWIN  49
#define NTOK  49
#define MROWS (BN*NWIN*NTOK)   // 115248
#define HID   512
#define QSCALE 0.17677669529663687f

// ---------------- scratch (device globals) ----------------
__device__ __nv_bfloat16 g_xw [(size_t)MROWS*CCH];   // LN1 out -> attn out -> LN2 out
__device__ __nv_bfloat16 g_big[(size_t)MROWS*HID];   // qkv (stride 384) then hidden (stride 512)
__device__ float         g_x2 [(size_t)MROWS*CCH];   // fp32 residual (x layout)
__device__ __nv_bfloat16 g_wts[196608];
__device__ float         g_bm [49*4*64*64];
#define WOFF_QKV 0
#define WOFF_PROJ 49152
#define WOFF_FC1  65536
#define WOFF_FC2  131072

// ---------------- asm helpers ----------------
__device__ __forceinline__ uint32_t smem_u32(const void* p) {
    return (uint32_t)__cvta_generic_to_shared(p);
}
__device__ __forceinline__ void cp_async16(uint32_t dst, const void* src, int sz) {
    asm volatile("cp.async.cg.shared.global [%0], [%1], 16, %2;"
                 :: "r"(dst), "l"(src), "r"(sz));
}
__device__ __forceinline__ void ldsm_x4(uint32_t r[4], uint32_t addr) {
    asm volatile("ldmatrix.sync.aligned.m8n8.x4.shared.b16 {%0,%1,%2,%3}, [%4];"
                 : "=r"(r[0]), "=r"(r[1]), "=r"(r[2]), "=r"(r[3]) : "r"(addr));
}
__device__ __forceinline__ void ldsm_x4_t(uint32_t r[4], uint32_t addr) {
    asm volatile("ldmatrix.sync.aligned.m8n8.x4.trans.shared.b16 {%0,%1,%2,%3}, [%4];"
                 : "=r"(r[0]), "=r"(r[1]), "=r"(r[2]), "=r"(r[3]) : "r"(addr));
}
__device__ __forceinline__ void mma_bf16(float c[4], const uint32_t a[4],
                                         uint32_t b0, uint32_t b1) {
    asm volatile("mma.sync.aligned.m16n8k16.row.col.f32.bf16.bf16.f32 "
                 "{%0,%1,%2,%3}, {%4,%5,%6,%7}, {%8,%9}, {%0,%1,%2,%3};"
                 : "+f"(c[0]), "+f"(c[1]), "+f"(c[2]), "+f"(c[3])
                 : "r"(a[0]), "r"(a[1]), "r"(a[2]), "r"(a[3]), "r"(b0), "r"(b1));
}

// ---------------- weight convert ----------------
__global__ void cvt_weights(const float* __restrict__ qkv_w, const float* __restrict__ proj_w,
                            const float* __restrict__ fc1_w, const float* __restrict__ fc2_w) {
    int i = blockIdx.x * 256 + threadIdx.x;
    if (i < 49152)       g_wts[WOFF_QKV  + i] = __float2bfloat16_rn(qkv_w[i]);
    if (i < 16384)       g_wts[WOFF_PROJ + i] = __float2bfloat16_rn(proj_w[i]);
    if (i < 65536) {     g_wts[WOFF_FC1  + i] = __float2bfloat16_rn(fc1_w[i]);
                         g_wts[WOFF_FC2  + i] = __float2bfloat16_rn(fc2_w[i]); }
}

// ---------------- bias+mask table ----------------
__device__ __forceinline__ int regn(int wq, int iq) {
    return (wq < 6) ? 0 : ((iq < 4) ? 1 : 2);
}
__global__ void build_bm(const float* __restrict__ rpb) {
    int w = blockIdx.x, h = blockIdx.y;
    int wh = w / 7, ww = w % 7;
    for (int e = threadIdx.x; e < 64 * 64; e += 256) {
        int n = e >> 6, m = e & 63;
        float v;
        if (n < 49 && m < 49) {
            int i1 = n / 7, j1 = n % 7, i2 = m / 7, j2 = m % 7;
            v = rpb[((i1 - i2 + 6) * 13 + (j1 - j2 + 6)) * 4 + h];
            int mwW = regn(wh, i2) * 3 + regn(ww, j2);
            int mwN = regn(i1, i2) * 3 + regn(j1, j2);
            if (mwW != mwN) v -= 100.f;
        } else {
            v = -1e9f;
        }
        g_bm[((size_t)(w * 4 + h) * 64 + n) * 64 + m] = v;
    }
}

// ---------------- LN1 + shift + window gather ----------------
__global__ void ln1_gather_kernel(const float* __restrict__ x,
                                  const float* __restrict__ w,
                                  const float* __restrict__ b) {
    int t = blockIdx.x, c = threadIdx.x;
    int bw = t / NTOK, n = t - bw * NTOK;
    int bb = bw / NWIN, wi = bw - bb * NWIN;
    int R  = (wi / 7) * 7 + n / 7;
    int Cl = (wi % 7) * 7 + n % 7;
    int sr = R + 3;  if (sr >= 49) sr -= 49;
    int sc = Cl + 3; if (sc >= 49) sc -= 49;
    float v = x[((size_t)bb * 2401 + sr * 49 + sc) * CCH + c];
    float s = v, s2 = v * v;
    #pragma unroll
    for (int o = 16; o > 0; o >>= 1) {
        s  += __shfl_xor_sync(0xffffffffu, s,  o);
        s2 += __shfl_xor_sync(0xffffffffu, s2, o);
    }
    __shared__ float red[8];
    int wid = c >> 5, lane = c & 31;
    if (lane == 0) { red[wid] = s; red[4 + wid] = s2; }
    __syncthreads();
    float ts  = red[0] + red[1] + red[2] + red[3];
    float ts2 = red[4] + red[5] + red[6] + red[7];
    float mean = ts * (1.f / 128.f);
    float var  = ts2 * (1.f / 128.f) - mean * mean;
    float rstd = rsqrtf(var + 1e-5f);
    g_xw[(size_t)t * CCH + c] = __float2bfloat16_rn((v - mean) * rstd * w[c] + b[c]);
}

// ---------------- LN2 ----------------
__global__ void ln2_kernel(const float* __restrict__ w,
                           const float* __restrict__ b) {
    int t = blockIdx.x, c = threadIdx.x;
    float v = g_x2[(size_t)t * CCH + c];
    float s = v, s2 = v * v;
    #pragma unroll
    for (int o = 16; o > 0; o >>= 1) {
        s  += __shfl_xor_sync(0xffffffffu, s,  o);
        s2 += __shfl_xor_sync(0xffffffffu, s2, o);
    }
    __shared__ float red[8];
    int wid = c >> 5, lane = c & 31;
    if (lane == 0) { red[wid] = s; red[4 + wid] = s2; }
    __syncthreads();
    float ts  = red[0] + red[1] + red[2] + red[3];
    float ts2 = red[4] + red[5] + red[6] + red[7];
    float mean = ts * (1.f / 128.f);
    float var  = ts2 * (1.f / 128.f) - mean * mean;
    float rstd = rsqrtf(var + 1e-5f);
    g_xw[(size_t)t * CCH + c] = __float2bfloat16_rn((v - mean) * rstd * w[c] + b[c]);
}

// ---------------- tensor-core attention (unchanged, passing) ----------------
__global__ void __launch_bounds__(128) attn_kernel() {
    int bw = blockIdx.x, h = blockIdx.y;
    int w  = bw % NWIN;
    int tid = threadIdx.x, lane = tid & 31, warp = tid >> 5;

    __shared__ __align__(16) uint8_t sQ[64 * 64];
    __shared__ __align__(16) uint8_t sK[64 * 64];
    __shared__ __align__(16) uint8_t sV[64 * 64];
    __shared__ __align__(16) uint8_t sP[64 * 128];

    uint32_t qb = smem_u32(sQ), kb = smem_u32(sK);
    uint32_t vb = smem_u32(sV), pb = smem_u32(sP);

    const __nv_bfloat16* base = g_big + (size_t)bw * NTOK * 384;
    for (int id = tid; id < 768; id += 128) {
        int op = id >> 8;
        int r  = (id >> 2) & 63;
        int c  = id & 3;
        uint32_t sb = (op == 0) ? qb : (op == 1) ? kb : vb;
        uint32_t dst = sb + r * 64 + ((c ^ ((r >> 1) & 3)) << 4);
        const __nv_bfloat16* src = base + (r < 49 ? r : 0) * 384 + op * 128 + h * 32 + c * 8;
        cp_async16(dst, src, r < 49 ? 16 : 0);
    }
    asm volatile("cp.async.commit_group;");
    asm volatile("cp.async.wait_group 0;");
    __syncthreads();

    int g = lane >> 2, tg = lane & 3;
    int m0 = warp * 16;

    float acc[8][4];
    #pragma unroll
    for (int i = 0; i < 8; i++)
        #pragma unroll
        for (int j = 0; j < 4; j++) acc[i][j] = 0.f;

    #pragma unroll
    for (int ks = 0; ks < 2; ks++) {
        uint32_t aF[4];
        {
            int r = m0 + (lane & 15);
            int c = 2 * ks + (lane >> 4);
            ldsm_x4(aF, qb + r * 64 + ((c ^ ((r >> 1) & 3)) << 4));
        }
        #pragma unroll
        for (int nfp = 0; nfp < 4; nfp++) {
            uint32_t bF[4];
            int r = nfp * 16 + (lane & 7) + ((lane >> 4) & 1) * 8;
            int c = 2 * ks + ((lane >> 3) & 1);
            ldsm_x4(bF, kb + r * 64 + ((c ^ ((r >> 1) & 3)) << 4));
            mma_bf16(acc[nfp * 2],     aF, bF[0], bF[1]);
            mma_bf16(acc[nfp * 2 + 1], aF, bF[2], bF[3]);
        }
    }

    const float* bm = g_bm + (size_t)(w * 4 + h) * 64 * 64;
    #pragma unroll
    for (int hh = 0; hh < 2; hh++) {
        int n = m0 + g + hh * 8;
        const float* bmr = bm + n * 64;
        float vals[16];
        #pragma unroll
        for (int nf = 0; nf < 8; nf++) {
            float2 bv = *(const float2*)(bmr + nf * 8 + tg * 2);
            vals[nf * 2]     = acc[nf][hh * 2]     + bv.x;
            vals[nf * 2 + 1] = acc[nf][hh * 2 + 1] + bv.y;
        }
        float mx = vals[0];
        #pragma unroll
        for (int i = 1; i < 16; i++) mx = fmaxf(mx, vals[i]);
        mx = fmaxf(mx, __shfl_xor_sync(0xffffffffu, mx, 1));
        mx = fmaxf(mx, __shfl_xor_sync(0xffffffffu, mx, 2));
        float sum = 0.f;
        #pragma unroll
        for (int i = 0; i < 16; i++) { vals[i] = __expf(vals[i] - mx); sum += vals[i]; }
        sum += __shfl_xor_sync(0xffffffffu, sum, 1);
        sum += __shfl_xor_sync(0xffffffffu, sum, 2);
        float inv = 1.f / sum;
        #pragma unroll
        for (int nf = 0; nf < 8; nf++) {
            __nv_bfloat162 p;
            p.x = __float2bfloat16_rn(vals[nf * 2] * inv);
            p.y = __float2bfloat16_rn(vals[nf * 2 + 1] * inv);
            *(uint32_t*)(sP + n * 128 + ((nf ^ (n & 7)) << 4) + tg * 4) = *(uint32_t*)&p;
        }
    }
    __syncwarp();

    float acc2[4][4];
    #pragma unroll
    for (int i = 0; i < 4; i++)
        #pragma unroll
        for (int j = 0; j < 4; j++) acc2[i][j] = 0.f;

    #pragma unroll
    for (int ks = 0; ks < 4; ks++) {
        uint32_t aF[4];
        {
            int r = m0 + (lane & 15);
            int c = 2 * ks + (lane >> 4);
            ldsm_x4(aF, pb + r * 128 + ((c ^ (r & 7)) << 4));
        }
        #pragma unroll
        for (int nfp = 0; nfp < 2; nfp++) {
            uint32_t bF[4];
            int rv = ks * 16 + (lane & 7) + ((lane >> 3) & 1) * 8;
            int cv = nfp * 2 + (lane >> 4);
            ldsm_x4_t(bF, vb + rv * 64 + ((cv ^ ((rv >> 1) & 3)) << 4));
            mma_bf16(acc2[nfp * 2],     aF, bF[0], bF[1]);
            mma_bf16(acc2[nfp * 2 + 1], aF, bF[2], bF[3]);
        }
    }

    #pragma unroll
    for (int hh = 0; hh < 2; hh++) {
        int n = m0 + g + hh * 8;
        if (n < 49) {
            __nv_bfloat16* dst = g_xw + ((size_t)bw * NTOK + n) * CCH + h * 32;
            #pragma unroll
            for (int nf = 0; nf < 4; nf++) {
                __nv_bfloat162 o;
                o.x = __float2bfloat16_rn(acc2[nf][hh * 2]);
                o.y = __float2bfloat16_rn(acc2[nf][hh * 2 + 1]);
                *(uint32_t*)(dst + nf * 8 + tg * 2) = *(uint32_t*)&o;
            }
        }
    }
}

// ---------------- high-occupancy bf16 GEMM: CTA 128x64, 8 warps, 4 CTAs/SM ----
// C = A[M,K] @ W[N,K]^T + bias.  3-stage cp.async pipeline, BK=32.
// Stage layout: [ A 128x32 (8KB) | W 64x32 (4KB) ] = 12KB; 3 stages = 36KB.
// EPI 0: qkv  EPI 1: proj+scatter+residual  EPI 2: fc1+GELU  EPI 3: fc2+residual
#define STG_B 12288
template <int EPI>
__global__ void __launch_bounds__(256, 4)
hgemm(const __nv_bfloat16* __restrict__ Wb, const float* __restrict__ bias,
      const float* __restrict__ aux, float* __restrict__ extC,
      int M, int K) {
    __shared__ __align__(16) uint8_t smem[3 * STG_B];
    const __nv_bfloat16* A = (EPI == 3) ? g_big : g_xw;

    int tid = threadIdx.x, lane = tid & 31, warp = tid >> 5;
    int row0 = blockIdx.x * 128, col0 = blockIdx.y * 64;
    int wm = warp >> 1, wn = warp & 1;    // 4 x 2 warp grid, each 32x32
    int g = lane >> 2, tg = lane & 3;

    float acc[2][4][4];
    #pragma unroll
    for (int i = 0; i < 2; i++)
        #pragma unroll
        for (int j = 0; j < 4; j++)
            #pragma unroll
            for (int e = 0; e < 4; e++) acc[i][j][e] = 0.f;

    uint32_t sbase = smem_u32(smem);
    const int nkt = K >> 5;

    auto load_tile = [&](int kt, int st) {
        uint32_t sa = sbase + st * STG_B;
        uint32_t sb = sa + 8192;
        // A: 128 rows x 4 chunks = 512 chunk-loads (2 per thread)
        #pragma unroll
        for (int h = 0; h < 2; h++) {
            int id = tid + h * 256;
            int r = id >> 2, c = id & 3;
            uint32_t off = r * 64 + ((c ^ ((r >> 1) & 3)) << 4);
            const __nv_bfloat16* ga = A + (size_t)(row0 + r) * K + kt * 32 + c * 8;
            cp_async16(sa + off, ga, (row0 + r) < M ? 16 : 0);
        }
        // W: 64 rows x 4 chunks = 256 chunk-loads (1 per thread)
        {
            int r = tid >> 2, c = tid & 3;
            uint32_t off = r * 64 + ((c ^ ((r >> 1) & 3)) << 4);
            const __nv_bfloat16* gb = Wb + (size_t)(col0 + r) * K + kt * 32 + c * 8;
            cp_async16(sb + off, gb, 16);
        }
        asm volatile("cp.async.commit_group;");
    };

    load_tile(0, 0);
    if (nkt > 1) load_tile(1, 1);

    for (int kt = 0; kt < nkt; kt++) {
        if (kt < nkt - 1) asm volatile("cp.async.wait_group 1;");
        else              asm volatile("cp.async.wait_group 0;");
        __syncthreads();
        if (kt + 2 < nkt) load_tile(kt + 2, (kt + 2) % 3);

        int st = kt % 3;
        uint32_t sa = sbase + st * STG_B;
        uint32_t sb = sa + 8192;
        #pragma unroll
        for (int ks = 0; ks < 2; ks++) {
            uint32_t aF[2][4], bF[2][4];
            #pragma unroll
            for (int mf = 0; mf < 2; mf++) {
                int r = wm * 32 + mf * 16 + (lane & 15);
                int c = 2 * ks + (lane >> 4);
                ldsm_x4(aF[mf], sa + r * 64 + ((c ^ ((r >> 1) & 3)) << 4));
            }
            #pragma unroll
            for (int nfp = 0; nfp < 2; nfp++) {
                int r = wn * 32 + nfp * 16 + (lane & 7) + ((lane >> 4) & 1) * 8;
                int c = 2 * ks + ((lane >> 3) & 1);
                ldsm_x4(bF[nfp], sb + r * 64 + ((c ^ ((r >> 1) & 3)) << 4));
            }
            #pragma unroll
            for (int mf = 0; mf < 2; mf++)
                #pragma unroll
                for (int nf = 0; nf < 4; nf++)
                    mma_bf16(acc[mf][nf], aF[mf],
                             bF[nf >> 1][(nf & 1) * 2], bF[nf >> 1][(nf & 1) * 2 + 1]);
        }
    }

    // ---- epilogue ----
    #pragma unroll
    for (int mf = 0; mf < 2; mf++) {
        #pragma unroll
        for (int hh = 0; hh < 2; hh++) {
            int r = row0 + wm * 32 + mf * 16 + g + hh * 8;
            if (r >= M) continue;
            size_t dest = 0;
            if (EPI == 1) {
                int bw = r / 49, tok = r - bw * 49;
                int bb = bw / 49, wi = bw - bb * 49;
                int R  = (wi / 7) * 7 + tok / 7;
                int Cl = (wi % 7) * 7 + tok % 7;
                int rr = R + 3;  if (rr >= 49) rr -= 49;
                int cc = Cl + 3; if (cc >= 49) cc -= 49;
                dest = ((size_t)bb * 2401 + rr * 49 + cc) * 128;
            }
            #pragma unroll
            for (int nf = 0; nf < 4; nf++) {
                #pragma unroll
                for (int e = 0; e < 2; e++) {
                    int n = col0 + wn * 32 + nf * 8 + tg * 2 + e;
                    float v = acc[mf][nf][hh * 2 + e] + bias[n];
                    if (EPI == 0) {
                        if (n < 128) v *= QSCALE;
                        g_big[(size_t)r * 384 + n] = __float2bfloat16_rn(v);
                    } else if (EPI == 1) {
                        g_x2[dest + n] = aux[dest + n] + v;
                    } else if (EPI == 2) {
                        v = 0.5f * v * (1.f + erff(v * 0.70710678118654752f));
                        g_big[(size_t)r * 512 + n] = __float2bfloat16_rn(v);
                    } else {
                        extC[(size_t)r * 128 + n] = g_x2[(size_t)r * 128 + n] + v;
                    }
                }
            }
        }
    }
}

// ---------------- launch ----------------
extern "C" void kernel_launch(void* const* d_in, const int* in_sizes, int n_in,
                              void* d_out, int out_size) {
    const float* x      = (const float*)d_in[0];
    const float* n1w    = (const float*)d_in[1];
    const float* n1b    = (const float*)d_in[2];
    const float* qkv_w  = (const float*)d_in[3];
    const float* qkv_b  = (const float*)d_in[4];
    const float* proj_w = (const float*)d_in[5];
    const float* proj_b = (const float*)d_in[6];
    const float* rpb    = (const float*)d_in[7];
    const float* n2w    = (const float*)d_in[8];
    const float* n2b    = (const float*)d_in[9];
    const float* fc1_w  = (const float*)d_in[10];
    const float* fc1_b  = (const float*)d_in[11];
    const float* fc2_w  = (const float*)d_in[12];
    const float* fc2_b  = (const float*)d_in[13];
    float* out = (float*)d_out;

    const int M = MROWS;
    const int gm = (M + 127) / 128;   // 901

    cvt_weights<<<256, 256>>>(qkv_w, proj_w, fc1_w, fc2_w);
    build_bm<<<dim3(49, 4), 256>>>(rpb);
    ln1_gather_kernel<<<M, 128>>>(x, n1w, n1b);

    __nv_bfloat16* wbase;
    cudaGetSymbolAddress((void**)&wbase, g_wts);

    hgemm<0><<<dim3(gm, 6), 256>>>(wbase + WOFF_QKV, qkv_b, nullptr, nullptr, M, 128);
    attn_kernel<<<dim3(BN * NWIN, 4), 128>>>();
    hgemm<1><<<dim3(gm, 2), 256>>>(wbase + WOFF_PROJ, proj_b, x, nullptr, M, 128);
    ln2_kernel<<<M, 128>>>(n2w, n2b);
    hgemm<2><<<dim3(gm, 8), 256>>>(wbase + WOFF_FC1, fc1_b, nullptr, nullptr, M, 128);
    hgemm<3><<<dim3(gm, 2), 256>>>(wbase + WOFF_FC2, fc2_b, nullptr, out, M, 512);
}

// round 10
// speedup vs baseline: 1.1153x; 1.0171x over previous
#include <cuda_runtime.h>
#include <cuda_fp16.h>
#include <math.h>
#include <stdint.h>

// ---------------- problem constants ----------------
#define BN    48
#define CCH   128
#define NWIN  49
#define NTOK  49
#define MROWS (BN*NWIN*NTOK)   // 115248
#define HID   512
#define QSCALE 0.17677669529663687f

// ---------------- scratch (device globals) ----------------
__device__ __half g_xw [(size_t)MROWS*CCH];   // LN1 out -> attn out -> LN2 out
__device__ __half g_big[(size_t)MROWS*HID];   // qkv (stride 384) then hidden (stride 512)
__device__ float  g_x2 [(size_t)MROWS*CCH];   // fp32 residual (x layout)
__device__ __half g_wts[196608];
__device__ float  g_bm [49*4*64*64];
#define WOFF_QKV 0
#define WOFF_PROJ 49152
#define WOFF_FC1  65536
#define WOFF_FC2  131072

// ---------------- asm helpers ----------------
__device__ __forceinline__ uint32_t smem_u32(const void* p) {
    return (uint32_t)__cvta_generic_to_shared(p);
}
__device__ __forceinline__ void cp_async16(uint32_t dst, const void* src, int sz) {
    asm volatile("cp.async.cg.shared.global [%0], [%1], 16, %2;"
                 :: "r"(dst), "l"(src), "r"(sz));
}
__device__ __forceinline__ void ldsm_x4(uint32_t r[4], uint32_t addr) {
    asm volatile("ldmatrix.sync.aligned.m8n8.x4.shared.b16 {%0,%1,%2,%3}, [%4];"
                 : "=r"(r[0]), "=r"(r[1]), "=r"(r[2]), "=r"(r[3]) : "r"(addr));
}
__device__ __forceinline__ void ldsm_x4_t(uint32_t r[4], uint32_t addr) {
    asm volatile("ldmatrix.sync.aligned.m8n8.x4.trans.shared.b16 {%0,%1,%2,%3}, [%4];"
                 : "=r"(r[0]), "=r"(r[1]), "=r"(r[2]), "=r"(r[3]) : "r"(addr));
}
// f16 inputs, fp32 accum (attention)
__device__ __forceinline__ void mma_f16f32(float c[4], const uint32_t a[4],
                                           uint32_t b0, uint32_t b1) {
    asm volatile("mma.sync.aligned.m16n8k16.row.col.f32.f16.f16.f32 "
                 "{%0,%1,%2,%3}, {%4,%5,%6,%7}, {%8,%9}, {%0,%1,%2,%3};"
                 : "+f"(c[0]), "+f"(c[1]), "+f"(c[2]), "+f"(c[3])
                 : "r"(a[0]), "r"(a[1]), "r"(a[2]), "r"(a[3]), "r"(b0), "r"(b1));
}
// f16 inputs, f16 accum (GEMMs) — the rate experiment
__device__ __forceinline__ void mma_f16h(uint32_t c[2], const uint32_t a[4],
                                         uint32_t b0, uint32_t b1) {
    asm volatile("mma.sync.aligned.m16n8k16.row.col.f16.f16.f16.f16 "
                 "{%0,%1}, {%2,%3,%4,%5}, {%6,%7}, {%0,%1};"
                 : "+r"(c[0]), "+r"(c[1])
                 : "r"(a[0]), "r"(a[1]), "r"(a[2]), "r"(a[3]), "r"(b0), "r"(b1));
}

// ---------------- weight convert ----------------
__global__ void cvt_weights(const float* __restrict__ qkv_w, const float* __restrict__ proj_w,
                            const float* __restrict__ fc1_w, const float* __restrict__ fc2_w) {
    int i = blockIdx.x * 256 + threadIdx.x;
    if (i < 49152)       g_wts[WOFF_QKV  + i] = __float2half_rn(qkv_w[i]);
    if (i < 16384)       g_wts[WOFF_PROJ + i] = __float2half_rn(proj_w[i]);
    if (i < 65536) {     g_wts[WOFF_FC1  + i] = __float2half_rn(fc1_w[i]);
                         g_wts[WOFF_FC2  + i] = __float2half_rn(fc2_w[i]); }
}

// ---------------- bias+mask table ----------------
__device__ __forceinline__ int regn(int wq, int iq) {
    return (wq < 6) ? 0 : ((iq < 4) ? 1 : 2);
}
__global__ void build_bm(const float* __restrict__ rpb) {
    int w = blockIdx.x, h = blockIdx.y;
    int wh = w / 7, ww = w % 7;
    for (int e = threadIdx.x; e < 64 * 64; e += 256) {
        int n = e >> 6, m = e & 63;
        float v;
        if (n < 49 && m < 49) {
            int i1 = n / 7, j1 = n % 7, i2 = m / 7, j2 = m % 7;
            v = rpb[((i1 - i2 + 6) * 13 + (j1 - j2 + 6)) * 4 + h];
            int mwW = regn(wh, i2) * 3 + regn(ww, j2);
            int mwN = regn(i1, i2) * 3 + regn(j1, j2);
            if (mwW != mwN) v -= 100.f;
        } else {
            v = -1e9f;
        }
        g_bm[((size_t)(w * 4 + h) * 64 + n) * 64 + m] = v;
    }
}

// ---------------- LN1 + shift + window gather ----------------
__global__ void ln1_gather_kernel(const float* __restrict__ x,
                                  const float* __restrict__ w,
                                  const float* __restrict__ b) {
    int t = blockIdx.x, c = threadIdx.x;
    int bw = t / NTOK, n = t - bw * NTOK;
    int bb = bw / NWIN, wi = bw - bb * NWIN;
    int R  = (wi / 7) * 7 + n / 7;
    int Cl = (wi % 7) * 7 + n % 7;
    int sr = R + 3;  if (sr >= 49) sr -= 49;
    int sc = Cl + 3; if (sc >= 49) sc -= 49;
    float v = x[((size_t)bb * 2401 + sr * 49 + sc) * CCH + c];
    float s = v, s2 = v * v;
    #pragma unroll
    for (int o = 16; o > 0; o >>= 1) {
        s  += __shfl_xor_sync(0xffffffffu, s,  o);
        s2 += __shfl_xor_sync(0xffffffffu, s2, o);
    }
    __shared__ float red[8];
    int wid = c >> 5, lane = c & 31;
    if (lane == 0) { red[wid] = s; red[4 + wid] = s2; }
    __syncthreads();
    float ts  = red[0] + red[1] + red[2] + red[3];
    float ts2 = red[4] + red[5] + red[6] + red[7];
    float mean = ts * (1.f / 128.f);
    float var  = ts2 * (1.f / 128.f) - mean * mean;
    float rstd = rsqrtf(var + 1e-5f);
    g_xw[(size_t)t * CCH + c] = __float2half_rn((v - mean) * rstd * w[c] + b[c]);
}

// ---------------- LN2 ----------------
__global__ void ln2_kernel(const float* __restrict__ w,
                           const float* __restrict__ b) {
    int t = blockIdx.x, c = threadIdx.x;
    float v = g_x2[(size_t)t * CCH + c];
    float s = v, s2 = v * v;
    #pragma unroll
    for (int o = 16; o > 0; o >>= 1) {
        s  += __shfl_xor_sync(0xffffffffu, s,  o);
        s2 += __shfl_xor_sync(0xffffffffu, s2, o);
    }
    __shared__ float red[8];
    int wid = c >> 5, lane = c & 31;
    if (lane == 0) { red[wid] = s; red[4 + wid] = s2; }
    __syncthreads();
    float ts  = red[0] + red[1] + red[2] + red[3];
    float ts2 = red[4] + red[5] + red[6] + red[7];
    float mean = ts * (1.f / 128.f);
    float var  = ts2 * (1.f / 128.f) - mean * mean;
    float rstd = rsqrtf(var + 1e-5f);
    g_xw[(size_t)t * CCH + c] = __float2half_rn((v - mean) * rstd * w[c] + b[c]);
}

// ---------------- tensor-core attention (f16 inputs, fp32 accum) ----------------
__global__ void __launch_bounds__(128) attn_kernel() {
    int bw = blockIdx.x, h = blockIdx.y;
    int w  = bw % NWIN;
    int tid = threadIdx.x, lane = tid & 31, warp = tid >> 5;

    __shared__ __align__(16) uint8_t sQ[64 * 64];
    __shared__ __align__(16) uint8_t sK[64 * 64];
    __shared__ __align__(16) uint8_t sV[64 * 64];
    __shared__ __align__(16) uint8_t sP[64 * 128];

    uint32_t qb = smem_u32(sQ), kb = smem_u32(sK);
    uint32_t vb = smem_u32(sV), pb = smem_u32(sP);

    const __half* base = g_big + (size_t)bw * NTOK * 384;
    for (int id = tid; id < 768; id += 128) {
        int op = id >> 8;
        int r  = (id >> 2) & 63;
        int c  = id & 3;
        uint32_t sb = (op == 0) ? qb : (op == 1) ? kb : vb;
        uint32_t dst = sb + r * 64 + ((c ^ ((r >> 1) & 3)) << 4);
        const __half* src = base + (r < 49 ? r : 0) * 384 + op * 128 + h * 32 + c * 8;
        cp_async16(dst, src, r < 49 ? 16 : 0);
    }
    asm volatile("cp.async.commit_group;");
    asm volatile("cp.async.wait_group 0;");
    __syncthreads();

    int g = lane >> 2, tg = lane & 3;
    int m0 = warp * 16;

    float acc[8][4];
    #pragma unroll
    for (int i = 0; i < 8; i++)
        #pragma unroll
        for (int j = 0; j < 4; j++) acc[i][j] = 0.f;

    #pragma unroll
    for (int ks = 0; ks < 2; ks++) {
        uint32_t aF[4];
        {
            int r = m0 + (lane & 15);
            int c = 2 * ks + (lane >> 4);
            ldsm_x4(aF, qb + r * 64 + ((c ^ ((r >> 1) & 3)) << 4));
        }
        #pragma unroll
        for (int nfp = 0; nfp < 4; nfp++) {
            uint32_t bF[4];
            int r = nfp * 16 + (lane & 7) + ((lane >> 4) & 1) * 8;
            int c = 2 * ks + ((lane >> 3) & 1);
            ldsm_x4(bF, kb + r * 64 + ((c ^ ((r >> 1) & 3)) << 4));
            mma_f16f32(acc[nfp * 2],     aF, bF[0], bF[1]);
            mma_f16f32(acc[nfp * 2 + 1], aF, bF[2], bF[3]);
        }
    }

    const float* bm = g_bm + (size_t)(w * 4 + h) * 64 * 64;
    #pragma unroll
    for (int hh = 0; hh < 2; hh++) {
        int n = m0 + g + hh * 8;
        const float* bmr = bm + n * 64;
        float vals[16];
        #pragma unroll
        for (int nf = 0; nf < 8; nf++) {
            float2 bv = *(const float2*)(bmr + nf * 8 + tg * 2);
            vals[nf * 2]     = acc[nf][hh * 2]     + bv.x;
            vals[nf * 2 + 1] = acc[nf][hh * 2 + 1] + bv.y;
        }
        float mx = vals[0];
        #pragma unroll
        for (int i = 1; i < 16; i++) mx = fmaxf(mx, vals[i]);
        mx = fmaxf(mx, __shfl_xor_sync(0xffffffffu, mx, 1));
        mx = fmaxf(mx, __shfl_xor_sync(0xffffffffu, mx, 2));
        float sum = 0.f;
        #pragma unroll
        for (int i = 0; i < 16; i++) { vals[i] = __expf(vals[i] - mx); sum += vals[i]; }
        sum += __shfl_xor_sync(0xffffffffu, sum, 1);
        sum += __shfl_xor_sync(0xffffffffu, sum, 2);
        float inv = 1.f / sum;
        #pragma unroll
        for (int nf = 0; nf < 8; nf++) {
            __half2 p;
            p.x = __float2half_rn(vals[nf * 2] * inv);
            p.y = __float2half_rn(vals[nf * 2 + 1] * inv);
            *(uint32_t*)(sP + n * 128 + ((nf ^ (n & 7)) << 4) + tg * 4) = *(uint32_t*)&p;
        }
    }
    __syncwarp();

    float acc2[4][4];
    #pragma unroll
    for (int i = 0; i < 4; i++)
        #pragma unroll
        for (int j = 0; j < 4; j++) acc2[i][j] = 0.f;

    #pragma unroll
    for (int ks = 0; ks < 4; ks++) {
        uint32_t aF[4];
        {
            int r = m0 + (lane & 15);
            int c = 2 * ks + (lane >> 4);
            ldsm_x4(aF, pb + r * 128 + ((c ^ (r & 7)) << 4));
        }
        #pragma unroll
        for (int nfp = 0; nfp < 2; nfp++) {
            uint32_t bF[4];
            int rv = ks * 16 + (lane & 7) + ((lane >> 3) & 1) * 8;
            int cv = nfp * 2 + (lane >> 4);
            ldsm_x4_t(bF, vb + rv * 64 + ((cv ^ ((rv >> 1) & 3)) << 4));
            mma_f16f32(acc2[nfp * 2],     aF, bF[0], bF[1]);
            mma_f16f32(acc2[nfp * 2 + 1], aF, bF[2], bF[3]);
        }
    }

    #pragma unroll
    for (int hh = 0; hh < 2; hh++) {
        int n = m0 + g + hh * 8;
        if (n < 49) {
            __half* dst = g_xw + ((size_t)bw * NTOK + n) * CCH + h * 32;
            #pragma unroll
            for (int nf = 0; nf < 4; nf++) {
                __half2 o;
                o.x = __float2half_rn(acc2[nf][hh * 2]);
                o.y = __float2half_rn(acc2[nf][hh * 2 + 1]);
                *(uint32_t*)(dst + nf * 8 + tg * 2) = *(uint32_t*)&o;
            }
        }
    }
}

// ---------------- f16-accum tensor-core GEMM with cp.async pipeline ----------------
// C = A[M,K](f16) @ W[N,K](f16)^T + bias, f16 accumulators across K.
// EPI 0: qkv  EPI 1: proj+scatter+residual  EPI 2: fc1+GELU  EPI 3: fc2+residual
#define BK 32
#define STAGES 3
#define TILE_B 8192

template <int EPI>
__global__ void __launch_bounds__(256, 2)
mma_gemm(const __half* __restrict__ Wb, const float* __restrict__ bias,
         const float* __restrict__ aux, float* __restrict__ extC,
         int M, int K) {
    __shared__ __align__(16) uint8_t smem[STAGES * 2 * TILE_B];

    const __half* A = (EPI == 3) ? g_big : g_xw;
    const int lda = (EPI == 3) ? 512 : 128;

    int tid = threadIdx.x, lane = tid & 31, warp = tid >> 5;
    int row0 = blockIdx.x * 128, col0 = blockIdx.y * 128;
    int wm = warp & 1, wn = warp >> 1;
    int g = lane >> 2, tg = lane & 3;

    // f16 accumulators: [mf][nf][hh] -> packed half2 (cols tg*2, tg*2+1; rows g + 8*hh)
    uint32_t accH[4][4][2];
    #pragma unroll
    for (int i = 0; i < 4; i++)
        #pragma unroll
        for (int j = 0; j < 4; j++) { accH[i][j][0] = 0u; accH[i][j][1] = 0u; }

    uint32_t sbase = smem_u32(smem);
    const int nkt = K / BK;

    auto load_tile = [&](int kt, int st) {
        uint32_t sa = sbase + st * 2 * TILE_B;
        uint32_t sb = sa + TILE_B;
        #pragma unroll
        for (int h = 0; h < 2; h++) {
            int id = tid + h * 256;
            int r = id >> 2, c = id & 3;
            uint32_t off = r * 64 + ((c ^ ((r >> 1) & 3)) << 4);
            const __half* ga = A + (size_t)(row0 + r) * lda + kt * BK + c * 8;
            cp_async16(sa + off, ga, (row0 + r) < M ? 16 : 0);
            const __half* gb = Wb + (size_t)(col0 + r) * K + kt * BK + c * 8;
            cp_async16(sb + off, gb, 16);
        }
        asm volatile("cp.async.commit_group;");
    };

    load_tile(0, 0);
    load_tile(1, 1);

    for (int kt = 0; kt < nkt; kt++) {
        if (kt < nkt - 1) asm volatile("cp.async.wait_group 1;");
        else              asm volatile("cp.async.wait_group 0;");
        __syncthreads();
        if (kt + 2 < nkt) load_tile(kt + 2, (kt + 2) % STAGES);

        int st = kt % STAGES;
        uint32_t sa = sbase + st * 2 * TILE_B;
        uint32_t sb = sa + TILE_B;
        #pragma unroll
        for (int ks = 0; ks < 2; ks++) {
            uint32_t aF[4][4], bF[2][4];
            #pragma unroll
            for (int mf = 0; mf < 4; mf++) {
                int r = wm * 64 + mf * 16 + (lane & 15);
                int c = 2 * ks + (lane >> 4);
                ldsm_x4(aF[mf], sa + r * 64 + ((c ^ ((r >> 1) & 3)) << 4));
            }
            #pragma unroll
            for (int nfp = 0; nfp < 2; nfp++) {
                int r = wn * 32 + nfp * 16 + (lane & 7) + ((lane >> 4) & 1) * 8;
                int c = 2 * ks + ((lane >> 3) & 1);
                ldsm_x4(bF[nfp], sb + r * 64 + ((c ^ ((r >> 1) & 3)) << 4));
            }
            #pragma unroll
            for (int mf = 0; mf < 4; mf++)
                #pragma unroll
                for (int nf = 0; nf < 4; nf++)
                    mma_f16h(accH[mf][nf], aF[mf],
                             bF[nf >> 1][(nf & 1) * 2], bF[nf >> 1][(nf & 1) * 2 + 1]);
        }
    }

    // ---- epilogue ----
    #pragma unroll
    for (int mf = 0; mf < 4; mf++) {
        #pragma unroll
        for (int hh = 0; hh < 2; hh++) {
            int r = row0 + wm * 64 + mf * 16 + g + hh * 8;
            if (r >= M) continue;
            size_t dest = 0;
            if (EPI == 1) {
                int bw = r / 49, tok = r - bw * 49;
                int bb = bw / 49, wi = bw - bb * 49;
                int R  = (wi / 7) * 7 + tok / 7;
                int Cl = (wi % 7) * 7 + tok % 7;
                int rr = R + 3;  if (rr >= 49) rr -= 49;
                int cc = Cl + 3; if (cc >= 49) cc -= 49;
                dest = ((size_t)bb * 2401 + rr * 49 + cc) * 128;
            }
            #pragma unroll
            for (int nf = 0; nf < 4; nf++) {
                __half2 hv = *reinterpret_cast<__half2*>(&accH[mf][nf][hh]);
                float pv[2] = { __low2float(hv), __high2float(hv) };
                #pragma unroll
                for (int e = 0; e < 2; e++) {
                    int n = col0 + wn * 32 + nf * 8 + tg * 2 + e;
                    float v = pv[e] + bias[n];
                    if (EPI == 0) {
                        if (n < 128) v *= QSCALE;
                        g_big[(size_t)r * 384 + n] = __float2half_rn(v);
                    } else if (EPI == 1) {
                        g_x2[dest + n] = aux[dest + n] + v;
                    } else if (EPI == 2) {
                        v = 0.5f * v * (1.f + erff(v * 0.70710678118654752f));
                        g_big[(size_t)r * 512 + n] = __float2half_rn(v);
                    } else {
                        extC[(size_t)r * 128 + n] = g_x2[(size_t)r * 128 + n] + v;
                    }
                }
            }
        }
    }
}

// ---------------- launch ----------------
extern "C" void kernel_launch(void* const* d_in, const int* in_sizes, int n_in,
                              void* d_out, int out_size) {
    const float* x      = (const float*)d_in[0];
    const float* n1w    = (const float*)d_in[1];
    const float* n1b    = (const float*)d_in[2];
    const float* qkv_w  = (const float*)d_in[3];
    const float* qkv_b  = (const float*)d_in[4];
    const float* proj_w = (const float*)d_in[5];
    const float* proj_b = (const float*)d_in[6];
    const float* rpb    = (const float*)d_in[7];
    const float* n2w    = (const float*)d_in[8];
    const float* n2b    = (const float*)d_in[9];
    const float* fc1_w  = (const float*)d_in[10];
    const float* fc1_b  = (const float*)d_in[11];
    const float* fc2_w  = (const float*)d_in[12];
    const float* fc2_b  = (const float*)d_in[13];
    float* out = (float*)d_out;

    const int M = MROWS;
    const int gm = (M + 127) / 128;   // 901

    cvt_weights<<<256, 256>>>(qkv_w, proj_w, fc1_w, fc2_w);
    build_bm<<<dim3(49, 4), 256>>>(rpb);
    ln1_gather_kernel<<<M, 128>>>(x, n1w, n1b);

    __half* wbase;
    cudaGetSymbolAddress((void**)&wbase, g_wts);

    mma_gemm<0><<<dim3(gm, 3), 256>>>(wbase + WOFF_QKV, qkv_b, nullptr, nullptr, M, 128);
    attn_kernel<<<dim3(BN * NWIN, 4), 128>>>();
    mma_gemm<1><<<dim3(gm, 1), 256>>>(wbase + WOFF_PROJ, proj_b, x, nullptr, M, 128);
    ln2_kernel<<<M, 128>>>(n2w, n2b);
    mma_gemm<2><<<dim3(gm, 4), 256>>>(wbase + WOFF_FC1, fc1_b, nullptr, nullptr, M, 128);
    mma_gemm<3><<<dim3(gm, 1), 256>>>(wbase + WOFF_FC2, fc2_b, nullptr, out, M, 512);
}

// round 11
// speedup vs baseline: 1.5568x; 1.3959x over previous
#include <cuda_runtime.h>
#include <cuda_fp16.h>
#include <math.h>
#include <stdint.h>

// ---------------- problem constants ----------------
#define BN    48
#define CCH   128
#define NWIN  49
#define NTOK  49
#define MROWS (BN*NWIN*NTOK)   // 115248
#define HID   512
#define QSCALE 0.17677669529663687f

// ---------------- scratch (device globals) ----------------
__device__ __half g_xw [(size_t)MROWS*CCH];   // LN1 out -> attn out (window order)
__device__ __half g_ln2[(size_t)MROWS*CCH];   // LN2 out (x layout) -> fc1 input
__device__ __half g_big[(size_t)MROWS*HID];   // qkv (stride 384) then hidden (stride 512)
__device__ float  g_x2 [(size_t)MROWS*CCH];   // fp32 residual (x layout)
__device__ __half g_wts[196608];
__device__ float  g_bm [49*4*64*64];
#define WOFF_QKV 0
#define WOFF_PROJ 49152
#define WOFF_FC1  65536
#define WOFF_FC2  131072

// ---------------- asm helpers ----------------
__device__ __forceinline__ uint32_t smem_u32(const void* p) {
    return (uint32_t)__cvta_generic_to_shared(p);
}
__device__ __forceinline__ void cp_async16(uint32_t dst, const void* src, int sz) {
    asm volatile("cp.async.cg.shared.global [%0], [%1], 16, %2;"
                 :: "r"(dst), "l"(src), "r"(sz));
}
__device__ __forceinline__ void ldsm_x4(uint32_t r[4], uint32_t addr) {
    asm volatile("ldmatrix.sync.aligned.m8n8.x4.shared.b16 {%0,%1,%2,%3}, [%4];"
                 : "=r"(r[0]), "=r"(r[1]), "=r"(r[2]), "=r"(r[3]) : "r"(addr));
}
__device__ __forceinline__ void ldsm_x4_t(uint32_t r[4], uint32_t addr) {
    asm volatile("ldmatrix.sync.aligned.m8n8.x4.trans.shared.b16 {%0,%1,%2,%3}, [%4];"
                 : "=r"(r[0]), "=r"(r[1]), "=r"(r[2]), "=r"(r[3]) : "r"(addr));
}
// f16 inputs, fp32 accum (attention)
__device__ __forceinline__ void mma_f16f32(float c[4], const uint32_t a[4],
                                           uint32_t b0, uint32_t b1) {
    asm volatile("mma.sync.aligned.m16n8k16.row.col.f32.f16.f16.f32 "
                 "{%0,%1,%2,%3}, {%4,%5,%6,%7}, {%8,%9}, {%0,%1,%2,%3};"
                 : "+f"(c[0]), "+f"(c[1]), "+f"(c[2]), "+f"(c[3])
                 : "r"(a[0]), "r"(a[1]), "r"(a[2]), "r"(a[3]), "r"(b0), "r"(b1));
}
// f16 inputs, f16 accum (GEMMs)
__device__ __forceinline__ void mma_f16h(uint32_t c[2], const uint32_t a[4],
                                         uint32_t b0, uint32_t b1) {
    asm volatile("mma.sync.aligned.m16n8k16.row.col.f16.f16.f16.f16 "
                 "{%0,%1}, {%2,%3,%4,%5}, {%6,%7}, {%0,%1};"
                 : "+r"(c[0]), "+r"(c[1])
                 : "r"(a[0]), "r"(a[1]), "r"(a[2]), "r"(a[3]), "r"(b0), "r"(b1));
}

// ---------------- weight convert ----------------
__global__ void cvt_weights(const float* __restrict__ qkv_w, const float* __restrict__ proj_w,
                            const float* __restrict__ fc1_w, const float* __restrict__ fc2_w) {
    int i = blockIdx.x * 256 + threadIdx.x;
    if (i < 49152)       g_wts[WOFF_QKV  + i] = __float2half_rn(qkv_w[i]);
    if (i < 16384)       g_wts[WOFF_PROJ + i] = __float2half_rn(proj_w[i]);
    if (i < 65536) {     g_wts[WOFF_FC1  + i] = __float2half_rn(fc1_w[i]);
                         g_wts[WOFF_FC2  + i] = __float2half_rn(fc2_w[i]); }
}

// ---------------- bias+mask table ----------------
__device__ __forceinline__ int regn(int wq, int iq) {
    return (wq < 6) ? 0 : ((iq < 4) ? 1 : 2);
}
__global__ void build_bm(const float* __restrict__ rpb) {
    int w = blockIdx.x, h = blockIdx.y;
    int wh = w / 7, ww = w % 7;
    for (int e = threadIdx.x; e < 64 * 64; e += 256) {
        int n = e >> 6, m = e & 63;
        float v;
        if (n < 49 && m < 49) {
            int i1 = n / 7, j1 = n % 7, i2 = m / 7, j2 = m % 7;
            v = rpb[((i1 - i2 + 6) * 13 + (j1 - j2 + 6)) * 4 + h];
            int mwW = regn(wh, i2) * 3 + regn(ww, j2);
            int mwN = regn(i1, i2) * 3 + regn(j1, j2);
            if (mwW != mwN) v -= 100.f;
        } else {
            v = -1e9f;
        }
        g_bm[((size_t)(w * 4 + h) * 64 + n) * 64 + m] = v;
    }
}

// ---------------- LN1 + shift + window gather ----------------
__global__ void ln1_gather_kernel(const float* __restrict__ x,
                                  const float* __restrict__ w,
                                  const float* __restrict__ b) {
    int t = blockIdx.x, c = threadIdx.x;
    int bw = t / NTOK, n = t - bw * NTOK;
    int bb = bw / NWIN, wi = bw - bb * NWIN;
    int R  = (wi / 7) * 7 + n / 7;
    int Cl = (wi % 7) * 7 + n % 7;
    int sr = R + 3;  if (sr >= 49) sr -= 49;
    int sc = Cl + 3; if (sc >= 49) sc -= 49;
    float v = x[((size_t)bb * 2401 + sr * 49 + sc) * CCH + c];
    float s = v, s2 = v * v;
    #pragma unroll
    for (int o = 16; o > 0; o >>= 1) {
        s  += __shfl_xor_sync(0xffffffffu, s,  o);
        s2 += __shfl_xor_sync(0xffffffffu, s2, o);
    }
    __shared__ float red[8];
    int wid = c >> 5, lane = c & 31;
    if (lane == 0) { red[wid] = s; red[4 + wid] = s2; }
    __syncthreads();
    float ts  = red[0] + red[1] + red[2] + red[3];
    float ts2 = red[4] + red[5] + red[6] + red[7];
    float mean = ts * (1.f / 128.f);
    float var  = ts2 * (1.f / 128.f) - mean * mean;
    float rstd = rsqrtf(var + 1e-5f);
    g_xw[(size_t)t * CCH + c] = __float2half_rn((v - mean) * rstd * w[c] + b[c]);
}

// ---------------- tensor-core attention (f16 inputs, fp32 accum) ----------------
__global__ void __launch_bounds__(128) attn_kernel() {
    int bw = blockIdx.x, h = blockIdx.y;
    int w  = bw % NWIN;
    int tid = threadIdx.x, lane = tid & 31, warp = tid >> 5;

    __shared__ __align__(16) uint8_t sQ[64 * 64];
    __shared__ __align__(16) uint8_t sK[64 * 64];
    __shared__ __align__(16) uint8_t sV[64 * 64];
    __shared__ __align__(16) uint8_t sP[64 * 128];

    uint32_t qb = smem_u32(sQ), kb = smem_u32(sK);
    uint32_t vb = smem_u32(sV), pb = smem_u32(sP);

    const __half* base = g_big + (size_t)bw * NTOK * 384;
    for (int id = tid; id < 768; id += 128) {
        int op = id >> 8;
        int r  = (id >> 2) & 63;
        int c  = id & 3;
        uint32_t sb = (op == 0) ? qb : (op == 1) ? kb : vb;
        uint32_t dst = sb + r * 64 + ((c ^ ((r >> 1) & 3)) << 4);
        const __half* src = base + (r < 49 ? r : 0) * 384 + op * 128 + h * 32 + c * 8;
        cp_async16(dst, src, r < 49 ? 16 : 0);
    }
    asm volatile("cp.async.commit_group;");
    asm volatile("cp.async.wait_group 0;");
    __syncthreads();

    int g = lane >> 2, tg = lane & 3;
    int m0 = warp * 16;

    float acc[8][4];
    #pragma unroll
    for (int i = 0; i < 8; i++)
        #pragma unroll
        for (int j = 0; j < 4; j++) acc[i][j] = 0.f;

    #pragma unroll
    for (int ks = 0; ks < 2; ks++) {
        uint32_t aF[4];
        {
            int r = m0 + (lane & 15);
            int c = 2 * ks + (lane >> 4);
            ldsm_x4(aF, qb + r * 64 + ((c ^ ((r >> 1) & 3)) << 4));
        }
        #pragma unroll
        for (int nfp = 0; nfp < 4; nfp++) {
            uint32_t bF[4];
            int r = nfp * 16 + (lane & 7) + ((lane >> 4) & 1) * 8;
            int c = 2 * ks + ((lane >> 3) & 1);
            ldsm_x4(bF, kb + r * 64 + ((c ^ ((r >> 1) & 3)) << 4));
            mma_f16f32(acc[nfp * 2],     aF, bF[0], bF[1]);
            mma_f16f32(acc[nfp * 2 + 1], aF, bF[2], bF[3]);
        }
    }

    const float* bm = g_bm + (size_t)(w * 4 + h) * 64 * 64;
    #pragma unroll
    for (int hh = 0; hh < 2; hh++) {
        int n = m0 + g + hh * 8;
        const float* bmr = bm + n * 64;
        float vals[16];
        #pragma unroll
        for (int nf = 0; nf < 8; nf++) {
            float2 bv = *(const float2*)(bmr + nf * 8 + tg * 2);
            vals[nf * 2]     = acc[nf][hh * 2]     + bv.x;
            vals[nf * 2 + 1] = acc[nf][hh * 2 + 1] + bv.y;
        }
        float mx = vals[0];
        #pragma unroll
        for (int i = 1; i < 16; i++) mx = fmaxf(mx, vals[i]);
        mx = fmaxf(mx, __shfl_xor_sync(0xffffffffu, mx, 1));
        mx = fmaxf(mx, __shfl_xor_sync(0xffffffffu, mx, 2));
        float sum = 0.f;
        #pragma unroll
        for (int i = 0; i < 16; i++) { vals[i] = __expf(vals[i] - mx); sum += vals[i]; }
        sum += __shfl_xor_sync(0xffffffffu, sum, 1);
        sum += __shfl_xor_sync(0xffffffffu, sum, 2);
        float inv = 1.f / sum;
        #pragma unroll
        for (int nf = 0; nf < 8; nf++) {
            __half2 p;
            p.x = __float2half_rn(vals[nf * 2] * inv);
            p.y = __float2half_rn(vals[nf * 2 + 1] * inv);
            *(uint32_t*)(sP + n * 128 + ((nf ^ (n & 7)) << 4) + tg * 4) = *(uint32_t*)&p;
        }
    }
    __syncwarp();

    float acc2[4][4];
    #pragma unroll
    for (int i = 0; i < 4; i++)
        #pragma unroll
        for (int j = 0; j < 4; j++) acc2[i][j] = 0.f;

    #pragma unroll
    for (int ks = 0; ks < 4; ks++) {
        uint32_t aF[4];
        {
            int r = m0 + (lane & 15);
            int c = 2 * ks + (lane >> 4);
            ldsm_x4(aF, pb + r * 128 + ((c ^ (r & 7)) << 4));
        }
        #pragma unroll
        for (int nfp = 0; nfp < 2; nfp++) {
            uint32_t bF[4];
            int rv = ks * 16 + (lane & 7) + ((lane >> 3) & 1) * 8;
            int cv = nfp * 2 + (lane >> 4);
            ldsm_x4_t(bF, vb + rv * 64 + ((cv ^ ((rv >> 1) & 3)) << 4));
            mma_f16f32(acc2[nfp * 2],     aF, bF[0], bF[1]);
            mma_f16f32(acc2[nfp * 2 + 1], aF, bF[2], bF[3]);
        }
    }

    #pragma unroll
    for (int hh = 0; hh < 2; hh++) {
        int n = m0 + g + hh * 8;
        if (n < 49) {
            __half* dst = g_xw + ((size_t)bw * NTOK + n) * CCH + h * 32;
            #pragma unroll
            for (int nf = 0; nf < 4; nf++) {
                __half2 o;
                o.x = __float2half_rn(acc2[nf][hh * 2]);
                o.y = __float2half_rn(acc2[nf][hh * 2 + 1]);
                *(uint32_t*)(dst + nf * 8 + tg * 2) = *(uint32_t*)&o;
            }
        }
    }
}

// ---------------- f16-accum tensor-core GEMM with cp.async pipeline ----------------
// EPI 0: qkv  EPI 1: proj+scatter+residual+FUSED LN2 (-> g_x2, g_ln2)
// EPI 2: fc1+GELU (A=g_ln2)  EPI 3: fc2+residual
#define BK 32
#define STAGES 3
#define TILE_B 8192

template <int EPI>
__global__ void __launch_bounds__(256, 2)
mma_gemm(const __half* __restrict__ Wb, const float* __restrict__ bias,
         const float* __restrict__ aux, float* __restrict__ extC,
         const float* __restrict__ n2w, const float* __restrict__ n2b,
         int M, int K) {
    __shared__ __align__(16) uint8_t smem[STAGES * 2 * TILE_B];
    __shared__ float sred[128 * 4 * 2];   // LN2 cross-warp partials (EPI 1 only)

    const __half* A = (EPI == 3) ? g_big : ((EPI == 2) ? g_ln2 : g_xw);
    const int lda = (EPI == 3) ? 512 : 128;

    int tid = threadIdx.x, lane = tid & 31, warp = tid >> 5;
    int row0 = blockIdx.x * 128, col0 = blockIdx.y * 128;
    int wm = warp & 1, wn = warp >> 1;
    int g = lane >> 2, tg = lane & 3;

    uint32_t accH[4][4][2];
    #pragma unroll
    for (int i = 0; i < 4; i++)
        #pragma unroll
        for (int j = 0; j < 4; j++) { accH[i][j][0] = 0u; accH[i][j][1] = 0u; }

    uint32_t sbase = smem_u32(smem);
    const int nkt = K / BK;

    auto load_tile = [&](int kt, int st) {
        uint32_t sa = sbase + st * 2 * TILE_B;
        uint32_t sb = sa + TILE_B;
        #pragma unroll
        for (int h = 0; h < 2; h++) {
            int id = tid + h * 256;
            int r = id >> 2, c = id & 3;
            uint32_t off = r * 64 + ((c ^ ((r >> 1) & 3)) << 4);
            const __half* ga = A + (size_t)(row0 + r) * lda + kt * BK + c * 8;
            cp_async16(sa + off, ga, (row0 + r) < M ? 16 : 0);
            const __half* gb = Wb + (size_t)(col0 + r) * K + kt * BK + c * 8;
            cp_async16(sb + off, gb, 16);
        }
        asm volatile("cp.async.commit_group;");
    };

    load_tile(0, 0);
    load_tile(1, 1);

    for (int kt = 0; kt < nkt; kt++) {
        if (kt < nkt - 1) asm volatile("cp.async.wait_group 1;");
        else              asm volatile("cp.async.wait_group 0;");
        __syncthreads();
        if (kt + 2 < nkt) load_tile(kt + 2, (kt + 2) % STAGES);

        int st = kt % STAGES;
        uint32_t sa = sbase + st * 2 * TILE_B;
        uint32_t sb = sa + TILE_B;
        #pragma unroll
        for (int ks = 0; ks < 2; ks++) {
            uint32_t aF[4][4], bF[2][4];
            #pragma unroll
            for (int mf = 0; mf < 4; mf++) {
                int r = wm * 64 + mf * 16 + (lane & 15);
                int c = 2 * ks + (lane >> 4);
                ldsm_x4(aF[mf], sa + r * 64 + ((c ^ ((r >> 1) & 3)) << 4));
            }
            #pragma unroll
            for (int nfp = 0; nfp < 2; nfp++) {
                int r = wn * 32 + nfp * 16 + (lane & 7) + ((lane >> 4) & 1) * 8;
                int c = 2 * ks + ((lane >> 3) & 1);
                ldsm_x4(bF[nfp], sb + r * 64 + ((c ^ ((r >> 1) & 3)) << 4));
            }
            #pragma unroll
            for (int mf = 0; mf < 4; mf++)
                #pragma unroll
                for (int nf = 0; nf < 4; nf++)
                    mma_f16h(accH[mf][nf], aF[mf],
                             bF[nf >> 1][(nf & 1) * 2], bF[nf >> 1][(nf & 1) * 2 + 1]);
        }
    }

    // ---- window-reverse scatter index helper (EPI 1) ----
    auto scatter_of = [](int r) -> size_t {
        int bw = r / 49, tok = r - bw * 49;
        int bb = bw / 49, wi = bw - bb * 49;
        int R  = (wi / 7) * 7 + tok / 7;
        int Cl = (wi % 7) * 7 + tok % 7;
        int rr = R + 3;  if (rr >= 49) rr -= 49;
        int cc = Cl + 3; if (cc >= 49) cc -= 49;
        return ((size_t)bb * 2401 + rr * 49 + cc) * 128;
    };

    if (EPI == 1) {
        // ---- phase A: residual + g_x2 write (float2) + row-sum partials ----
        #pragma unroll
        for (int mf = 0; mf < 4; mf++) {
            #pragma unroll
            for (int hh = 0; hh < 2; hh++) {
                int rl = wm * 64 + mf * 16 + g + hh * 8;
                int r = row0 + rl;
                bool ok = r < M;
                size_t dest = scatter_of(ok ? r : (M - 1));
                float s = 0.f, s2 = 0.f;
                #pragma unroll
                for (int nf = 0; nf < 4; nf++) {
                    int n = wn * 32 + nf * 8 + tg * 2;
                    __half2 hv = *reinterpret_cast<__half2*>(&accH[mf][nf][hh]);
                    float2 a2 = *reinterpret_cast<const float2*>(aux + dest + n);
                    float2 b2 = *reinterpret_cast<const float2*>(bias + n);
                    float2 v;
                    v.x = __low2float(hv)  + b2.x + a2.x;
                    v.y = __high2float(hv) + b2.y + a2.y;
                    if (ok) *reinterpret_cast<float2*>(g_x2 + dest + n) = v;
                    s  += v.x + v.y;
                    s2 += v.x * v.x + v.y * v.y;
                }
                // quad reduce (lanes tg 0..3 share row)
                s  += __shfl_xor_sync(0xffffffffu, s,  1);
                s2 += __shfl_xor_sync(0xffffffffu, s2, 1);
                s  += __shfl_xor_sync(0xffffffffu, s,  2);
                s2 += __shfl_xor_sync(0xffffffffu, s2, 2);
                if (tg == 0) {
                    sred[(rl * 4 + wn) * 2]     = s;
                    sred[(rl * 4 + wn) * 2 + 1] = s2;
                }
            }
        }
        __syncthreads();
        // ---- phase B: LN over row, write g_ln2 (half2) ----
        #pragma unroll
        for (int mf = 0; mf < 4; mf++) {
            #pragma unroll
            for (int hh = 0; hh < 2; hh++) {
                int rl = wm * 64 + mf * 16 + g + hh * 8;
                int r = row0 + rl;
                bool ok = r < M;
                size_t dest = scatter_of(ok ? r : (M - 1));
                float ts = 0.f, ts2 = 0.f;
                #pragma unroll
                for (int q = 0; q < 4; q++) {
                    ts  += sred[(rl * 4 + q) * 2];
                    ts2 += sred[(rl * 4 + q) * 2 + 1];
                }
                float mean = ts * (1.f / 128.f);
                float var  = ts2 * (1.f / 128.f) - mean * mean;
                float rstd = rsqrtf(var + 1e-5f);
                if (ok) {
                    #pragma unroll
                    for (int nf = 0; nf < 4; nf++) {
                        int n = wn * 32 + nf * 8 + tg * 2;
                        float2 v = *reinterpret_cast<const float2*>(g_x2 + dest + n);
                        float2 w2 = *reinterpret_cast<const float2*>(n2w + n);
                        float2 c2 = *reinterpret_cast<const float2*>(n2b + n);
                        __half2 o;
                        o.x = __float2half_rn((v.x - mean) * rstd * w2.x + c2.x);
                        o.y = __float2half_rn((v.y - mean) * rstd * w2.y + c2.y);
                        *reinterpret_cast<uint32_t*>(g_ln2 + dest + n) = *(uint32_t*)&o;
                    }
                }
            }
        }
    } else {
        #pragma unroll
        for (int mf = 0; mf < 4; mf++) {
            #pragma unroll
            for (int hh = 0; hh < 2; hh++) {
                int r = row0 + wm * 64 + mf * 16 + g + hh * 8;
                if (r >= M) continue;
                #pragma unroll
                for (int nf = 0; nf < 4; nf++) {
                    int n = col0 + wn * 32 + nf * 8 + tg * 2;
                    __half2 hv = *reinterpret_cast<__half2*>(&accH[mf][nf][hh]);
                    float2 b2 = *reinterpret_cast<const float2*>(bias + n);
                    float vx = __low2float(hv)  + b2.x;
                    float vy = __high2float(hv) + b2.y;
                    if (EPI == 0) {
                        if (n < 128) { vx *= QSCALE; vy *= QSCALE; }
                        __half2 o; o.x = __float2half_rn(vx); o.y = __float2half_rn(vy);
                        *reinterpret_cast<uint32_t*>(g_big + (size_t)r * 384 + n) = *(uint32_t*)&o;
                    } else if (EPI == 2) {
                        vx = 0.5f * vx * (1.f + erff(vx * 0.70710678118654752f));
                        vy = 0.5f * vy * (1.f + erff(vy * 0.70710678118654752f));
                        __half2 o; o.x = __float2half_rn(vx); o.y = __float2half_rn(vy);
                        *reinterpret_cast<uint32_t*>(g_big + (size_t)r * 512 + n) = *(uint32_t*)&o;
                    } else {
                        float2 x2v = *reinterpret_cast<const float2*>(g_x2 + (size_t)r * 128 + n);
                        float2 o; o.x = vx + x2v.x; o.y = vy + x2v.y;
                        *reinterpret_cast<float2*>(extC + (size_t)r * 128 + n) = o;
                    }
                }
            }
        }
    }
}

// ---------------- launch ----------------
extern "C" void kernel_launch(void* const* d_in, const int* in_sizes, int n_in,
                              void* d_out, int out_size) {
    const float* x      = (const float*)d_in[0];
    const float* n1w    = (const float*)d_in[1];
    const float* n1b    = (const float*)d_in[2];
    const float* qkv_w  = (const float*)d_in[3];
    const float* qkv_b  = (const float*)d_in[4];
    const float* proj_w = (const float*)d_in[5];
    const float* proj_b = (const float*)d_in[6];
    const float* rpb    = (const float*)d_in[7];
    const float* n2w    = (const float*)d_in[8];
    const float* n2b    = (const float*)d_in[9];
    const float* fc1_w  = (const float*)d_in[10];
    const float* fc1_b  = (const float*)d_in[11];
    const float* fc2_w  = (const float*)d_in[12];
    const float* fc2_b  = (const float*)d_in[13];
    float* out = (float*)d_out;

    const int M = MROWS;
    const int gm = (M + 127) / 128;   // 901

    cvt_weights<<<256, 256>>>(qkv_w, proj_w, fc1_w, fc2_w);
    build_bm<<<dim3(49, 4), 256>>>(rpb);
    ln1_gather_kernel<<<M, 128>>>(x, n1w, n1b);

    __half* wbase;
    cudaGetSymbolAddress((void**)&wbase, g_wts);

    mma_gemm<0><<<dim3(gm, 3), 256>>>(wbase + WOFF_QKV, qkv_b, nullptr, nullptr, nullptr, nullptr, M, 128);
    attn_kernel<<<dim3(BN * NWIN, 4), 128>>>();
    mma_gemm<1><<<dim3(gm, 1), 256>>>(wbase + WOFF_PROJ, proj_b, x, nullptr, n2w, n2b, M, 128);
    mma_gemm<2><<<dim3(gm, 4), 256>>>(wbase + WOFF_FC1, fc1_b, nullptr, nullptr, nullptr, nullptr, M, 128);
    mma_gemm<3><<<dim3(gm, 1), 256>>>(wbase + WOFF_FC2, fc2_b, nullptr, out, nullptr, nullptr, M, 512);
}

// round 12
// speedup vs baseline: 1.5636x; 1.0044x over previous
#include <cuda_runtime.h>
#include <cuda_fp16.h>
#include <math.h>
#include <stdint.h>

// ---------------- problem constants ----------------
#define BN    48
#define CCH   128
#define NWIN  49
#define NTOK  49
#define MROWS (BN*NWIN*NTOK)   // 115248
#define HID   512
#define QSCALE 0.17677669529663687f

// ---------------- scratch (device globals) ----------------
__device__ __half g_xw [(size_t)MROWS*CCH];   // LN1 out -> attn out (window order)
__device__ __half g_ln2[(size_t)MROWS*CCH];   // LN2 out (x layout) -> fc1 input
__device__ __half g_big[(size_t)MROWS*HID];   // qkv (stride 384) then hidden (stride 512)
__device__ float  g_x2 [(size_t)MROWS*CCH];   // fp32 residual (x layout)
__device__ __half g_wts[196608];
__device__ float  g_bm [49*4*64*64];
#define WOFF_QKV 0
#define WOFF_PROJ 49152
#define WOFF_FC1  65536
#define WOFF_FC2  131072

// ---------------- asm helpers ----------------
__device__ __forceinline__ uint32_t smem_u32(const void* p) {
    return (uint32_t)__cvta_generic_to_shared(p);
}
__device__ __forceinline__ void cp_async16(uint32_t dst, const void* src, int sz) {
    asm volatile("cp.async.cg.shared.global [%0], [%1], 16, %2;"
                 :: "r"(dst), "l"(src), "r"(sz));
}
__device__ __forceinline__ void ldsm_x4(uint32_t r[4], uint32_t addr) {
    asm volatile("ldmatrix.sync.aligned.m8n8.x4.shared.b16 {%0,%1,%2,%3}, [%4];"
                 : "=r"(r[0]), "=r"(r[1]), "=r"(r[2]), "=r"(r[3]) : "r"(addr));
}
__device__ __forceinline__ void ldsm_x4_t(uint32_t r[4], uint32_t addr) {
    asm volatile("ldmatrix.sync.aligned.m8n8.x4.trans.shared.b16 {%0,%1,%2,%3}, [%4];"
                 : "=r"(r[0]), "=r"(r[1]), "=r"(r[2]), "=r"(r[3]) : "r"(addr));
}
// f16 inputs, fp32 accum (attention)
__device__ __forceinline__ void mma_f16f32(float c[4], const uint32_t a[4],
                                           uint32_t b0, uint32_t b1) {
    asm volatile("mma.sync.aligned.m16n8k16.row.col.f32.f16.f16.f32 "
                 "{%0,%1,%2,%3}, {%4,%5,%6,%7}, {%8,%9}, {%0,%1,%2,%3};"
                 : "+f"(c[0]), "+f"(c[1]), "+f"(c[2]), "+f"(c[3])
                 : "r"(a[0]), "r"(a[1]), "r"(a[2]), "r"(a[3]), "r"(b0), "r"(b1));
}
// f16 inputs, f16 accum (GEMMs)
__device__ __forceinline__ void mma_f16h(uint32_t c[2], const uint32_t a[4],
                                         uint32_t b0, uint32_t b1) {
    asm volatile("mma.sync.aligned.m16n8k16.row.col.f16.f16.f16.f16 "
                 "{%0,%1}, {%2,%3,%4,%5}, {%6,%7}, {%0,%1};"
                 : "+r"(c[0]), "+r"(c[1])
                 : "r"(a[0]), "r"(a[1]), "r"(a[2]), "r"(a[3]), "r"(b0), "r"(b1));
}

// ---------------- weight convert ----------------
__global__ void cvt_weights(const float* __restrict__ qkv_w, const float* __restrict__ proj_w,
                            const float* __restrict__ fc1_w, const float* __restrict__ fc2_w) {
    int i = blockIdx.x * 256 + threadIdx.x;
    if (i < 49152)       g_wts[WOFF_QKV  + i] = __float2half_rn(qkv_w[i]);
    if (i < 16384)       g_wts[WOFF_PROJ + i] = __float2half_rn(proj_w[i]);
    if (i < 65536) {     g_wts[WOFF_FC1  + i] = __float2half_rn(fc1_w[i]);
                         g_wts[WOFF_FC2  + i] = __float2half_rn(fc2_w[i]); }
}

// ---------------- bias+mask table ----------------
__device__ __forceinline__ int regn(int wq, int iq) {
    return (wq < 6) ? 0 : ((iq < 4) ? 1 : 2);
}
__global__ void build_bm(const float* __restrict__ rpb) {
    int w = blockIdx.x, h = blockIdx.y;
    int wh = w / 7, ww = w % 7;
    for (int e = threadIdx.x; e < 64 * 64; e += 256) {
        int n = e >> 6, m = e & 63;
        float v;
        if (n < 49 && m < 49) {
            int i1 = n / 7, j1 = n % 7, i2 = m / 7, j2 = m % 7;
            v = rpb[((i1 - i2 + 6) * 13 + (j1 - j2 + 6)) * 4 + h];
            int mwW = regn(wh, i2) * 3 + regn(ww, j2);
            int mwN = regn(i1, i2) * 3 + regn(j1, j2);
            if (mwW != mwN) v -= 100.f;
        } else {
            v = -1e9f;
        }
        g_bm[((size_t)(w * 4 + h) * 64 + n) * 64 + m] = v;
    }
}

// ---------------- LN1 + shift + window gather ----------------
__global__ void ln1_gather_kernel(const float* __restrict__ x,
                                  const float* __restrict__ w,
                                  const float* __restrict__ b) {
    int t = blockIdx.x, c = threadIdx.x;
    int bw = t / NTOK, n = t - bw * NTOK;
    int bb = bw / NWIN, wi = bw - bb * NWIN;
    int R  = (wi / 7) * 7 + n / 7;
    int Cl = (wi % 7) * 7 + n % 7;
    int sr = R + 3;  if (sr >= 49) sr -= 49;
    int sc = Cl + 3; if (sc >= 49) sc -= 49;
    float v = x[((size_t)bb * 2401 + sr * 49 + sc) * CCH + c];
    float s = v, s2 = v * v;
    #pragma unroll
    for (int o = 16; o > 0; o >>= 1) {
        s  += __shfl_xor_sync(0xffffffffu, s,  o);
        s2 += __shfl_xor_sync(0xffffffffu, s2, o);
    }
    __shared__ float red[8];
    int wid = c >> 5, lane = c & 31;
    if (lane == 0) { red[wid] = s; red[4 + wid] = s2; }
    __syncthreads();
    float ts  = red[0] + red[1] + red[2] + red[3];
    float ts2 = red[4] + red[5] + red[6] + red[7];
    float mean = ts * (1.f / 128.f);
    float var  = ts2 * (1.f / 128.f) - mean * mean;
    float rstd = rsqrtf(var + 1e-5f);
    g_xw[(size_t)t * CCH + c] = __float2half_rn((v - mean) * rstd * w[c] + b[c]);
}

// ---------------- tensor-core attention (f16 inputs, fp32 accum) ----------------
__global__ void __launch_bounds__(128) attn_kernel() {
    int bw = blockIdx.x, h = blockIdx.y;
    int w  = bw % NWIN;
    int tid = threadIdx.x, lane = tid & 31, warp = tid >> 5;

    __shared__ __align__(16) uint8_t sQ[64 * 64];
    __shared__ __align__(16) uint8_t sK[64 * 64];
    __shared__ __align__(16) uint8_t sV[64 * 64];
    __shared__ __align__(16) uint8_t sP[64 * 128];

    uint32_t qb = smem_u32(sQ), kb = smem_u32(sK);
    uint32_t vb = smem_u32(sV), pb = smem_u32(sP);

    const __half* base = g_big + (size_t)bw * NTOK * 384;
    for (int id = tid; id < 768; id += 128) {
        int op = id >> 8;
        int r  = (id >> 2) & 63;
        int c  = id & 3;
        uint32_t sb = (op == 0) ? qb : (op == 1) ? kb : vb;
        uint32_t dst = sb + r * 64 + ((c ^ ((r >> 1) & 3)) << 4);
        const __half* src = base + (r < 49 ? r : 0) * 384 + op * 128 + h * 32 + c * 8;
        cp_async16(dst, src, r < 49 ? 16 : 0);
    }
    asm volatile("cp.async.commit_group;");
    asm volatile("cp.async.wait_group 0;");
    __syncthreads();

    int g = lane >> 2, tg = lane & 3;
    int m0 = warp * 16;

    float acc[8][4];
    #pragma unroll
    for (int i = 0; i < 8; i++)
        #pragma unroll
        for (int j = 0; j < 4; j++) acc[i][j] = 0.f;

    #pragma unroll
    for (int ks = 0; ks < 2; ks++) {
        uint32_t aF[4];
        {
            int r = m0 + (lane & 15);
            int c = 2 * ks + (lane >> 4);
            ldsm_x4(aF, qb + r * 64 + ((c ^ ((r >> 1) & 3)) << 4));
        }
        #pragma unroll
        for (int nfp = 0; nfp < 4; nfp++) {
            uint32_t bF[4];
            int r = nfp * 16 + (lane & 7) + ((lane >> 4) & 1) * 8;
            int c = 2 * ks + ((lane >> 3) & 1);
            ldsm_x4(bF, kb + r * 64 + ((c ^ ((r >> 1) & 3)) << 4));
            mma_f16f32(acc[nfp * 2],     aF, bF[0], bF[1]);
            mma_f16f32(acc[nfp * 2 + 1], aF, bF[2], bF[3]);
        }
    }

    const float* bm = g_bm + (size_t)(w * 4 + h) * 64 * 64;
    #pragma unroll
    for (int hh = 0; hh < 2; hh++) {
        int n = m0 + g + hh * 8;
        const float* bmr = bm + n * 64;
        float vals[16];
        #pragma unroll
        for (int nf = 0; nf < 8; nf++) {
            float2 bv = *(const float2*)(bmr + nf * 8 + tg * 2);
            vals[nf * 2]     = acc[nf][hh * 2]     + bv.x;
            vals[nf * 2 + 1] = acc[nf][hh * 2 + 1] + bv.y;
        }
        float mx = vals[0];
        #pragma unroll
        for (int i = 1; i < 16; i++) mx = fmaxf(mx, vals[i]);
        mx = fmaxf(mx, __shfl_xor_sync(0xffffffffu, mx, 1));
        mx = fmaxf(mx, __shfl_xor_sync(0xffffffffu, mx, 2));
        float sum = 0.f;
        #pragma unroll
        for (int i = 0; i < 16; i++) { vals[i] = __expf(vals[i] - mx); sum += vals[i]; }
        sum += __shfl_xor_sync(0xffffffffu, sum, 1);
        sum += __shfl_xor_sync(0xffffffffu, sum, 2);
        float inv = 1.f / sum;
        #pragma unroll
        for (int nf = 0; nf < 8; nf++) {
            __half2 p;
            p.x = __float2half_rn(vals[nf * 2] * inv);
            p.y = __float2half_rn(vals[nf * 2 + 1] * inv);
            *(uint32_t*)(sP + n * 128 + ((nf ^ (n & 7)) << 4) + tg * 4) = *(uint32_t*)&p;
        }
    }
    __syncwarp();

    float acc2[4][4];
    #pragma unroll
    for (int i = 0; i < 4; i++)
        #pragma unroll
        for (int j = 0; j < 4; j++) acc2[i][j] = 0.f;

    #pragma unroll
    for (int ks = 0; ks < 4; ks++) {
        uint32_t aF[4];
        {
            int r = m0 + (lane & 15);
            int c = 2 * ks + (lane >> 4);
            ldsm_x4(aF, pb + r * 128 + ((c ^ (r & 7)) << 4));
        }
        #pragma unroll
        for (int nfp = 0; nfp < 2; nfp++) {
            uint32_t bF[4];
            int rv = ks * 16 + (lane & 7) + ((lane >> 3) & 1) * 8;
            int cv = nfp * 2 + (lane >> 4);
            ldsm_x4_t(bF, vb + rv * 64 + ((cv ^ ((rv >> 1) & 3)) << 4));
            mma_f16f32(acc2[nfp * 2],     aF, bF[0], bF[1]);
            mma_f16f32(acc2[nfp * 2 + 1], aF, bF[2], bF[3]);
        }
    }

    #pragma unroll
    for (int hh = 0; hh < 2; hh++) {
        int n = m0 + g + hh * 8;
        if (n < 49) {
            __half* dst = g_xw + ((size_t)bw * NTOK + n) * CCH + h * 32;
            #pragma unroll
            for (int nf = 0; nf < 4; nf++) {
                __half2 o;
                o.x = __float2half_rn(acc2[nf][hh * 2]);
                o.y = __float2half_rn(acc2[nf][hh * 2 + 1]);
                *(uint32_t*)(dst + nf * 8 + tg * 2) = *(uint32_t*)&o;
            }
        }
    }
}

// ---------------- proj GEMM (128x128) with fused LN2 (EPI 1 path of R11) -------
#define BK 32
#define STAGES 3
#define TILE_B 8192

__global__ void __launch_bounds__(256, 2)
proj_gemm(const __half* __restrict__ Wb, const float* __restrict__ bias,
          const float* __restrict__ aux,
          const float* __restrict__ n2w, const float* __restrict__ n2b, int M) {
    __shared__ __align__(16) uint8_t smem[STAGES * 2 * TILE_B];
    __shared__ float sred[128 * 4 * 2];

    const __half* A = g_xw;
    const int K = 128;

    int tid = threadIdx.x, lane = tid & 31, warp = tid >> 5;
    int row0 = blockIdx.x * 128;
    int wm = warp & 1, wn = warp >> 1;
    int g = lane >> 2, tg = lane & 3;

    uint32_t accH[4][4][2];
    #pragma unroll
    for (int i = 0; i < 4; i++)
        #pragma unroll
        for (int j = 0; j < 4; j++) { accH[i][j][0] = 0u; accH[i][j][1] = 0u; }

    uint32_t sbase = smem_u32(smem);
    const int nkt = K / BK;

    auto load_tile = [&](int kt, int st) {
        uint32_t sa = sbase + st * 2 * TILE_B;
        uint32_t sb = sa + TILE_B;
        #pragma unroll
        for (int h = 0; h < 2; h++) {
            int id = tid + h * 256;
            int r = id >> 2, c = id & 3;
            uint32_t off = r * 64 + ((c ^ ((r >> 1) & 3)) << 4);
            const __half* ga = A + (size_t)(row0 + r) * K + kt * BK + c * 8;
            cp_async16(sa + off, ga, (row0 + r) < M ? 16 : 0);
            const __half* gb = Wb + (size_t)r * K + kt * BK + c * 8;
            cp_async16(sb + off, gb, 16);
        }
        asm volatile("cp.async.commit_group;");
    };

    load_tile(0, 0);
    load_tile(1, 1);

    for (int kt = 0; kt < nkt; kt++) {
        if (kt < nkt - 1) asm volatile("cp.async.wait_group 1;");
        else              asm volatile("cp.async.wait_group 0;");
        __syncthreads();
        if (kt + 2 < nkt) load_tile(kt + 2, (kt + 2) % STAGES);

        int st = kt % STAGES;
        uint32_t sa = sbase + st * 2 * TILE_B;
        uint32_t sb = sa + TILE_B;
        #pragma unroll
        for (int ks = 0; ks < 2; ks++) {
            uint32_t aF[4][4], bF[2][4];
            #pragma unroll
            for (int mf = 0; mf < 4; mf++) {
                int r = wm * 64 + mf * 16 + (lane & 15);
                int c = 2 * ks + (lane >> 4);
                ldsm_x4(aF[mf], sa + r * 64 + ((c ^ ((r >> 1) & 3)) << 4));
            }
            #pragma unroll
            for (int nfp = 0; nfp < 2; nfp++) {
                int r = wn * 32 + nfp * 16 + (lane & 7) + ((lane >> 4) & 1) * 8;
                int c = 2 * ks + ((lane >> 3) & 1);
                ldsm_x4(bF[nfp], sb + r * 64 + ((c ^ ((r >> 1) & 3)) << 4));
            }
            #pragma unroll
            for (int mf = 0; mf < 4; mf++)
                #pragma unroll
                for (int nf = 0; nf < 4; nf++)
                    mma_f16h(accH[mf][nf], aF[mf],
                             bF[nf >> 1][(nf & 1) * 2], bF[nf >> 1][(nf & 1) * 2 + 1]);
        }
    }

    auto scatter_of = [](int r) -> size_t {
        int bw = r / 49, tok = r - bw * 49;
        int bb = bw / 49, wi = bw - bb * 49;
        int R  = (wi / 7) * 7 + tok / 7;
        int Cl = (wi % 7) * 7 + tok % 7;
        int rr = R + 3;  if (rr >= 49) rr -= 49;
        int cc = Cl + 3; if (cc >= 49) cc -= 49;
        return ((size_t)bb * 2401 + rr * 49 + cc) * 128;
    };

    // phase A: residual + g_x2 + partial sums
    #pragma unroll
    for (int mf = 0; mf < 4; mf++) {
        #pragma unroll
        for (int hh = 0; hh < 2; hh++) {
            int rl = wm * 64 + mf * 16 + g + hh * 8;
            int r = row0 + rl;
            bool ok = r < M;
            size_t dest = scatter_of(ok ? r : (M - 1));
            float s = 0.f, s2 = 0.f;
            #pragma unroll
            for (int nf = 0; nf < 4; nf++) {
                int n = wn * 32 + nf * 8 + tg * 2;
                __half2 hv = *reinterpret_cast<__half2*>(&accH[mf][nf][hh]);
                float2 a2 = *reinterpret_cast<const float2*>(aux + dest + n);
                float2 b2 = *reinterpret_cast<const float2*>(bias + n);
                float2 v;
                v.x = __low2float(hv)  + b2.x + a2.x;
                v.y = __high2float(hv) + b2.y + a2.y;
                if (ok) *reinterpret_cast<float2*>(g_x2 + dest + n) = v;
                s  += v.x + v.y;
                s2 += v.x * v.x + v.y * v.y;
            }
            s  += __shfl_xor_sync(0xffffffffu, s,  1);
            s2 += __shfl_xor_sync(0xffffffffu, s2, 1);
            s  += __shfl_xor_sync(0xffffffffu, s,  2);
            s2 += __shfl_xor_sync(0xffffffffu, s2, 2);
            if (tg == 0) {
                sred[(rl * 4 + wn) * 2]     = s;
                sred[(rl * 4 + wn) * 2 + 1] = s2;
            }
        }
    }
    __syncthreads();
    // phase B: LN2 -> g_ln2
    #pragma unroll
    for (int mf = 0; mf < 4; mf++) {
        #pragma unroll
        for (int hh = 0; hh < 2; hh++) {
            int rl = wm * 64 + mf * 16 + g + hh * 8;
            int r = row0 + rl;
            bool ok = r < M;
            size_t dest = scatter_of(ok ? r : (M - 1));
            float ts = 0.f, ts2 = 0.f;
            #pragma unroll
            for (int q = 0; q < 4; q++) {
                ts  += sred[(rl * 4 + q) * 2];
                ts2 += sred[(rl * 4 + q) * 2 + 1];
            }
            float mean = ts * (1.f / 128.f);
            float var  = ts2 * (1.f / 128.f) - mean * mean;
            float rstd = rsqrtf(var + 1e-5f);
            if (ok) {
                #pragma unroll
                for (int nf = 0; nf < 4; nf++) {
                    int n = wn * 32 + nf * 8 + tg * 2;
                    float2 v = *reinterpret_cast<const float2*>(g_x2 + dest + n);
                    float2 w2 = *reinterpret_cast<const float2*>(n2w + n);
                    float2 c2 = *reinterpret_cast<const float2*>(n2b + n);
                    __half2 o;
                    o.x = __float2half_rn((v.x - mean) * rstd * w2.x + c2.x);
                    o.y = __float2half_rn((v.y - mean) * rstd * w2.y + c2.y);
                    *reinterpret_cast<uint32_t*>(g_ln2 + dest + n) = *(uint32_t*)&o;
                }
            }
        }
    }
}

// ---------------- high-occupancy GEMM: 128x64 tile, 8 warps of 32x32, 4 CTAs/SM --
// EPI 0: qkv  EPI 2: fc1+GELU (A=g_ln2)  EPI 3: fc2+residual (A=g_big, K=512)
#define STG_B 12288
template <int EPI>
__global__ void __launch_bounds__(256, 4)
hgemm(const __half* __restrict__ Wb, const float* __restrict__ bias,
      float* __restrict__ extC, int M, int K) {
    __shared__ __align__(16) uint8_t smem[3 * STG_B];
    const __half* A = (EPI == 3) ? g_big : ((EPI == 2) ? g_ln2 : g_xw);

    int tid = threadIdx.x, lane = tid & 31, warp = tid >> 5;
    int row0 = blockIdx.x * 128, col0 = blockIdx.y * 64;
    int wm = warp >> 1, wn = warp & 1;
    int g = lane >> 2, tg = lane & 3;

    uint32_t accH[2][4][2];
    #pragma unroll
    for (int i = 0; i < 2; i++)
        #pragma unroll
        for (int j = 0; j < 4; j++) { accH[i][j][0] = 0u; accH[i][j][1] = 0u; }

    uint32_t sbase = smem_u32(smem);
    const int nkt = K >> 5;

    auto load_tile = [&](int kt, int st) {
        uint32_t sa = sbase + st * STG_B;
        uint32_t sb = sa + 8192;
        #pragma unroll
        for (int h = 0; h < 2; h++) {
            int id = tid + h * 256;
            int r = id >> 2, c = id & 3;
            uint32_t off = r * 64 + ((c ^ ((r >> 1) & 3)) << 4);
            const __half* ga = A + (size_t)(row0 + r) * K + kt * 32 + c * 8;
            cp_async16(sa + off, ga, (row0 + r) < M ? 16 : 0);
        }
        {
            int r = tid >> 2, c = tid & 3;
            uint32_t off = r * 64 + ((c ^ ((r >> 1) & 3)) << 4);
            const __half* gb = Wb + (size_t)(col0 + r) * K + kt * 32 + c * 8;
            cp_async16(sb + off, gb, 16);
        }
        asm volatile("cp.async.commit_group;");
    };

    load_tile(0, 0);
    if (nkt > 1) load_tile(1, 1);

    for (int kt = 0; kt < nkt; kt++) {
        if (kt < nkt - 1) asm volatile("cp.async.wait_group 1;");
        else              asm volatile("cp.async.wait_group 0;");
        __syncthreads();
        if (kt + 2 < nkt) load_tile(kt + 2, (kt + 2) % 3);

        int st = kt % 3;
        uint32_t sa = sbase + st * STG_B;
        uint32_t sb = sa + 8192;
        #pragma unroll
        for (int ks = 0; ks < 2; ks++) {
            uint32_t aF[2][4], bF[2][4];
            #pragma unroll
            for (int mf = 0; mf < 2; mf++) {
                int r = wm * 32 + mf * 16 + (lane & 15);
                int c = 2 * ks + (lane >> 4);
                ldsm_x4(aF[mf], sa + r * 64 + ((c ^ ((r >> 1) & 3)) << 4));
            }
            #pragma unroll
            for (int nfp = 0; nfp < 2; nfp++) {
                int r = wn * 32 + nfp * 16 + (lane & 7) + ((lane >> 4) & 1) * 8;
                int c = 2 * ks + ((lane >> 3) & 1);
                ldsm_x4(bF[nfp], sb + r * 64 + ((c ^ ((r >> 1) & 3)) << 4));
            }
            #pragma unroll
            for (int mf = 0; mf < 2; mf++)
                #pragma unroll
                for (int nf = 0; nf < 4; nf++)
                    mma_f16h(accH[mf][nf], aF[mf],
                             bF[nf >> 1][(nf & 1) * 2], bF[nf >> 1][(nf & 1) * 2 + 1]);
        }
    }

    // ---- vectorized epilogue ----
    #pragma unroll
    for (int mf = 0; mf < 2; mf++) {
        #pragma unroll
        for (int hh = 0; hh < 2; hh++) {
            int r = row0 + wm * 32 + mf * 16 + g + hh * 8;
            if (r >= M) continue;
            #pragma unroll
            for (int nf = 0; nf < 4; nf++) {
                int n = col0 + wn * 32 + nf * 8 + tg * 2;
                __half2 hv = *reinterpret_cast<__half2*>(&accH[mf][nf][hh]);
                float2 b2 = *reinterpret_cast<const float2*>(bias + n);
                float vx = __low2float(hv)  + b2.x;
                float vy = __high2float(hv) + b2.y;
                if (EPI == 0) {
                    if (n < 128) { vx *= QSCALE; vy *= QSCALE; }
                    __half2 o; o.x = __float2half_rn(vx); o.y = __float2half_rn(vy);
                    *reinterpret_cast<uint32_t*>(g_big + (size_t)r * 384 + n) = *(uint32_t*)&o;
                } else if (EPI == 2) {
                    vx = 0.5f * vx * (1.f + erff(vx * 0.70710678118654752f));
                    vy = 0.5f * vy * (1.f + erff(vy * 0.70710678118654752f));
                    __half2 o; o.x = __float2half_rn(vx); o.y = __float2half_rn(vy);
                    *reinterpret_cast<uint32_t*>(g_big + (size_t)r * 512 + n) = *(uint32_t*)&o;
                } else {
                    float2 x2v = *reinterpret_cast<const float2*>(g_x2 + (size_t)r * 128 + n);
                    float2 o; o.x = vx + x2v.x; o.y = vy + x2v.y;
                    *reinterpret_cast<float2*>(extC + (size_t)r * 128 + n) = o;
                }
            }
        }
    }
}

// ---------------- launch ----------------
extern "C" void kernel_launch(void* const* d_in, const int* in_sizes, int n_in,
                              void* d_out, int out_size) {
    const float* x      = (const float*)d_in[0];
    const float* n1w    = (const float*)d_in[1];
    const float* n1b    = (const float*)d_in[2];
    const float* qkv_w  = (const float*)d_in[3];
    const float* qkv_b  = (const float*)d_in[4];
    const float* proj_w = (const float*)d_in[5];
    const float* proj_b = (const float*)d_in[6];
    const float* rpb    = (const float*)d_in[7];
    const float* n2w    = (const float*)d_in[8];
    const float* n2b    = (const float*)d_in[9];
    const float* fc1_w  = (const float*)d_in[10];
    const float* fc1_b  = (const float*)d_in[11];
    const float* fc2_w  = (const float*)d_in[12];
    const float* fc2_b  = (const float*)d_in[13];
    float* out = (float*)d_out;

    const int M = MROWS;
    const int gm = (M + 127) / 128;   // 901

    cvt_weights<<<256, 256>>>(qkv_w, proj_w, fc1_w, fc2_w);
    build_bm<<<dim3(49, 4), 256>>>(rpb);
    ln1_gather_kernel<<<M, 128>>>(x, n1w, n1b);

    __half* wbase;
    cudaGetSymbolAddress((void**)&wbase, g_wts);

    hgemm<0><<<dim3(gm, 6), 256>>>(wbase + WOFF_QKV, qkv_b, nullptr, M, 128);
    attn_kernel<<<dim3(BN * NWIN, 4), 128>>>();
    proj_gemm<<<dim3(gm, 1), 256>>>(wbase + WOFF_PROJ, proj_b, x, n2w, n2b, M);
    hgemm<2><<<dim3(gm, 8), 256>>>(wbase + WOFF_FC1, fc1_b, nullptr, M, 128);
    hgemm<3><<<dim3(gm, 2), 256>>>(wbase + WOFF_FC2, fc2_b, out, M, 512);
}

// round 13
// speedup vs baseline: 1.6332x; 1.0445x over previous
#include <cuda_runtime.h>
#include <cuda_fp16.h>
#include <math.h>
#include <stdint.h>

// ---------------- problem constants ----------------
#define BN    48
#define CCH   128
#define NWIN  49
#define NTOK  49
#define MROWS (BN*NWIN*NTOK)   // 115248
#define HID   512
#define QSCALE 0.17677669529663687f

// ---------------- scratch (device globals) ----------------
__device__ __half g_xw [(size_t)MROWS*CCH];   // LN1 out -> attn out (window order)
__device__ __half g_ln2[(size_t)MROWS*CCH];   // LN2 out (x layout) -> fc1 input
__device__ __half g_big[(size_t)MROWS*HID];   // qkv (stride 384) then hidden (stride 512)
__device__ float  g_x2 [(size_t)MROWS*CCH];   // fp32 residual (x layout)
__device__ __half g_wts[196608];
__device__ float  g_qkvb[384];                // pre-scaled qkv bias
__device__ float  g_bm [49*4*64*64];
#define WOFF_QKV 0
#define WOFF_PROJ 49152
#define WOFF_FC1  65536
#define WOFF_FC2  131072

// ---------------- asm helpers ----------------
__device__ __forceinline__ uint32_t smem_u32(const void* p) {
    return (uint32_t)__cvta_generic_to_shared(p);
}
__device__ __forceinline__ void cp_async16(uint32_t dst, const void* src, int sz) {
    asm volatile("cp.async.cg.shared.global [%0], [%1], 16, %2;"
                 :: "r"(dst), "l"(src), "r"(sz));
}
__device__ __forceinline__ void ldsm_x4(uint32_t r[4], uint32_t addr) {
    asm volatile("ldmatrix.sync.aligned.m8n8.x4.shared.b16 {%0,%1,%2,%3}, [%4];"
                 : "=r"(r[0]), "=r"(r[1]), "=r"(r[2]), "=r"(r[3]) : "r"(addr));
}
__device__ __forceinline__ void ldsm_x4_t(uint32_t r[4], uint32_t addr) {
    asm volatile("ldmatrix.sync.aligned.m8n8.x4.trans.shared.b16 {%0,%1,%2,%3}, [%4];"
                 : "=r"(r[0]), "=r"(r[1]), "=r"(r[2]), "=r"(r[3]) : "r"(addr));
}
__device__ __forceinline__ void mma_f16f32(float c[4], const uint32_t a[4],
                                           uint32_t b0, uint32_t b1) {
    asm volatile("mma.sync.aligned.m16n8k16.row.col.f32.f16.f16.f32 "
                 "{%0,%1,%2,%3}, {%4,%5,%6,%7}, {%8,%9}, {%0,%1,%2,%3};"
                 : "+f"(c[0]), "+f"(c[1]), "+f"(c[2]), "+f"(c[3])
                 : "r"(a[0]), "r"(a[1]), "r"(a[2]), "r"(a[3]), "r"(b0), "r"(b1));
}
__device__ __forceinline__ void mma_f16h(uint32_t c[2], const uint32_t a[4],
                                         uint32_t b0, uint32_t b1) {
    asm volatile("mma.sync.aligned.m16n8k16.row.col.f16.f16.f16.f16 "
                 "{%0,%1}, {%2,%3,%4,%5}, {%6,%7}, {%0,%1};"
                 : "+r"(c[0]), "+r"(c[1])
                 : "r"(a[0]), "r"(a[1]), "r"(a[2]), "r"(a[3]), "r"(b0), "r"(b1));
}

// ---------------- weight convert (q rows pre-scaled) ----------------
__global__ void cvt_weights(const float* __restrict__ qkv_w, const float* __restrict__ proj_w,
                            const float* __restrict__ fc1_w, const float* __restrict__ fc2_w,
                            const float* __restrict__ qkv_b) {
    int i = blockIdx.x * 256 + threadIdx.x;
    if (i < 49152) {
        float v = qkv_w[i];
        if (i < 16384) v *= QSCALE;          // rows 0..127 = q
        g_wts[WOFF_QKV + i] = __float2half_rn(v);
    }
    if (i < 16384)       g_wts[WOFF_PROJ + i] = __float2half_rn(proj_w[i]);
    if (i < 65536) {     g_wts[WOFF_FC1  + i] = __float2half_rn(fc1_w[i]);
                         g_wts[WOFF_FC2  + i] = __float2half_rn(fc2_w[i]); }
    if (i < 384)         g_qkvb[i] = qkv_b[i] * (i < 128 ? QSCALE : 1.f);
}

// ---------------- bias+mask table ----------------
__device__ __forceinline__ int regn(int wq, int iq) {
    return (wq < 6) ? 0 : ((iq < 4) ? 1 : 2);
}
__global__ void build_bm(const float* __restrict__ rpb) {
    int w = blockIdx.x, h = blockIdx.y;
    int wh = w / 7, ww = w % 7;
    for (int e = threadIdx.x; e < 64 * 64; e += 256) {
        int n = e >> 6, m = e & 63;
        float v;
        if (n < 49 && m < 49) {
            int i1 = n / 7, j1 = n % 7, i2 = m / 7, j2 = m % 7;
            v = rpb[((i1 - i2 + 6) * 13 + (j1 - j2 + 6)) * 4 + h];
            int mwW = regn(wh, i2) * 3 + regn(ww, j2);
            int mwN = regn(i1, i2) * 3 + regn(j1, j2);
            if (mwW != mwN) v -= 100.f;
        } else {
            v = -1e9f;
        }
        g_bm[((size_t)(w * 4 + h) * 64 + n) * 64 + m] = v;
    }
}

// ---------------- LN1 + shift + window gather ----------------
__global__ void ln1_gather_kernel(const float* __restrict__ x,
                                  const float* __restrict__ w,
                                  const float* __restrict__ b) {
    int t = blockIdx.x, c = threadIdx.x;
    int bw = t / NTOK, n = t - bw * NTOK;
    int bb = bw / NWIN, wi = bw - bb * NWIN;
    int R  = (wi / 7) * 7 + n / 7;
    int Cl = (wi % 7) * 7 + n % 7;
    int sr = R + 3;  if (sr >= 49) sr -= 49;
    int sc = Cl + 3; if (sc >= 49) sc -= 49;
    float v = x[((size_t)bb * 2401 + sr * 49 + sc) * CCH + c];
    float s = v, s2 = v * v;
    #pragma unroll
    for (int o = 16; o > 0; o >>= 1) {
        s  += __shfl_xor_sync(0xffffffffu, s,  o);
        s2 += __shfl_xor_sync(0xffffffffu, s2, o);
    }
    __shared__ float red[8];
    int wid = c >> 5, lane = c & 31;
    if (lane == 0) { red[wid] = s; red[4 + wid] = s2; }
    __syncthreads();
    float ts  = red[0] + red[1] + red[2] + red[3];
    float ts2 = red[4] + red[5] + red[6] + red[7];
    float mean = ts * (1.f / 128.f);
    float var  = ts2 * (1.f / 128.f) - mean * mean;
    float rstd = rsqrtf(var + 1e-5f);
    g_xw[(size_t)t * CCH + c] = __float2half_rn((v - mean) * rstd * w[c] + b[c]);
}

// ---------------- tensor-core attention (f16 inputs, fp32 accum) ----------------
__global__ void __launch_bounds__(128) attn_kernel() {
    int bw = blockIdx.x, h = blockIdx.y;
    int w  = bw % NWIN;
    int tid = threadIdx.x, lane = tid & 31, warp = tid >> 5;

    __shared__ __align__(16) uint8_t sQ[64 * 64];
    __shared__ __align__(16) uint8_t sK[64 * 64];
    __shared__ __align__(16) uint8_t sV[64 * 64];
    __shared__ __align__(16) uint8_t sP[64 * 128];

    uint32_t qb = smem_u32(sQ), kb = smem_u32(sK);
    uint32_t vb = smem_u32(sV), pb = smem_u32(sP);

    const __half* base = g_big + (size_t)bw * NTOK * 384;
    for (int id = tid; id < 768; id += 128) {
        int op = id >> 8;
        int r  = (id >> 2) & 63;
        int c  = id & 3;
        uint32_t sb = (op == 0) ? qb : (op == 1) ? kb : vb;
        uint32_t dst = sb + r * 64 + ((c ^ ((r >> 1) & 3)) << 4);
        const __half* src = base + (r < 49 ? r : 0) * 384 + op * 128 + h * 32 + c * 8;
        cp_async16(dst, src, r < 49 ? 16 : 0);
    }
    asm volatile("cp.async.commit_group;");
    asm volatile("cp.async.wait_group 0;");
    __syncthreads();

    int g = lane >> 2, tg = lane & 3;
    int m0 = warp * 16;

    float acc[8][4];
    #pragma unroll
    for (int i = 0; i < 8; i++)
        #pragma unroll
        for (int j = 0; j < 4; j++) acc[i][j] = 0.f;

    #pragma unroll
    for (int ks = 0; ks < 2; ks++) {
        uint32_t aF[4];
        {
            int r = m0 + (lane & 15);
            int c = 2 * ks + (lane >> 4);
            ldsm_x4(aF, qb + r * 64 + ((c ^ ((r >> 1) & 3)) << 4));
        }
        #pragma unroll
        for (int nfp = 0; nfp < 4; nfp++) {
            uint32_t bF[4];
            int r = nfp * 16 + (lane & 7) + ((lane >> 4) & 1) * 8;
            int c = 2 * ks + ((lane >> 3) & 1);
            ldsm_x4(bF, kb + r * 64 + ((c ^ ((r >> 1) & 3)) << 4));
            mma_f16f32(acc[nfp * 2],     aF, bF[0], bF[1]);
            mma_f16f32(acc[nfp * 2 + 1], aF, bF[2], bF[3]);
        }
    }

    const float* bm = g_bm + (size_t)(w * 4 + h) * 64 * 64;
    #pragma unroll
    for (int hh = 0; hh < 2; hh++) {
        int n = m0 + g + hh * 8;
        const float* bmr = bm + n * 64;
        float vals[16];
        #pragma unroll
        for (int nf = 0; nf < 8; nf++) {
            float2 bv = *(const float2*)(bmr + nf * 8 + tg * 2);
            vals[nf * 2]     = acc[nf][hh * 2]     + bv.x;
            vals[nf * 2 + 1] = acc[nf][hh * 2 + 1] + bv.y;
        }
        float mx = vals[0];
        #pragma unroll
        for (int i = 1; i < 16; i++) mx = fmaxf(mx, vals[i]);
        mx = fmaxf(mx, __shfl_xor_sync(0xffffffffu, mx, 1));
        mx = fmaxf(mx, __shfl_xor_sync(0xffffffffu, mx, 2));
        float sum = 0.f;
        #pragma unroll
        for (int i = 0; i < 16; i++) { vals[i] = __expf(vals[i] - mx); sum += vals[i]; }
        sum += __shfl_xor_sync(0xffffffffu, sum, 1);
        sum += __shfl_xor_sync(0xffffffffu, sum, 2);
        float inv = 1.f / sum;
        #pragma unroll
        for (int nf = 0; nf < 8; nf++) {
            __half2 p;
            p.x = __float2half_rn(vals[nf * 2] * inv);
            p.y = __float2half_rn(vals[nf * 2 + 1] * inv);
            *(uint32_t*)(sP + n * 128 + ((nf ^ (n & 7)) << 4) + tg * 4) = *(uint32_t*)&p;
        }
    }
    __syncwarp();

    float acc2[4][4];
    #pragma unroll
    for (int i = 0; i < 4; i++)
        #pragma unroll
        for (int j = 0; j < 4; j++) acc2[i][j] = 0.f;

    #pragma unroll
    for (int ks = 0; ks < 4; ks++) {
        uint32_t aF[4];
        {
            int r = m0 + (lane & 15);
            int c = 2 * ks + (lane >> 4);
            ldsm_x4(aF, pb + r * 128 + ((c ^ (r & 7)) << 4));
        }
        #pragma unroll
        for (int nfp = 0; nfp < 2; nfp++) {
            uint32_t bF[4];
            int rv = ks * 16 + (lane & 7) + ((lane >> 3) & 1) * 8;
            int cv = nfp * 2 + (lane >> 4);
            ldsm_x4_t(bF, vb + rv * 64 + ((cv ^ ((rv >> 1) & 3)) << 4));
            mma_f16f32(acc2[nfp * 2],     aF, bF[0], bF[1]);
            mma_f16f32(acc2[nfp * 2 + 1], aF, bF[2], bF[3]);
        }
    }

    #pragma unroll
    for (int hh = 0; hh < 2; hh++) {
        int n = m0 + g + hh * 8;
        if (n < 49) {
            __half* dst = g_xw + ((size_t)bw * NTOK + n) * CCH + h * 32;
            #pragma unroll
            for (int nf = 0; nf < 4; nf++) {
                __half2 o;
                o.x = __float2half_rn(acc2[nf][hh * 2]);
                o.y = __float2half_rn(acc2[nf][hh * 2 + 1]);
                *(uint32_t*)(dst + nf * 8 + tg * 2) = *(uint32_t*)&o;
            }
        }
    }
}

// ---------------- f16-accum GEMM, compile-time K, fully unrolled mainloop --------
// EPI 0: qkv  EPI 1: proj+scatter+residual+fused LN2  EPI 2: fc1+GELU  EPI 3: fc2+res
#define BK 32
#define STAGES 3
#define TILE_B 8192

template <int EPI, int K>
__global__ void __launch_bounds__(256, 2)
mma_gemm(const __half* __restrict__ Wb, const float* __restrict__ bias,
         const float* __restrict__ aux, float* __restrict__ extC,
         const float* __restrict__ n2w, const float* __restrict__ n2b, int M) {
    __shared__ __align__(16) uint8_t smem[STAGES * 2 * TILE_B];
    __shared__ float sred[128 * 4 * 2];

    const __half* A = (EPI == 3) ? g_big : ((EPI == 2) ? g_ln2 : g_xw);
    constexpr int nkt = K / BK;

    int tid = threadIdx.x, lane = tid & 31, warp = tid >> 5;
    int row0 = blockIdx.x * 128, col0 = blockIdx.y * 128;
    int wm = warp & 1, wn = warp >> 1;
    int g = lane >> 2, tg = lane & 3;

    uint32_t accH[4][4][2];
    #pragma unroll
    for (int i = 0; i < 4; i++)
        #pragma unroll
        for (int j = 0; j < 4; j++) { accH[i][j][0] = 0u; accH[i][j][1] = 0u; }

    uint32_t sbase = smem_u32(smem);

    // hoisted per-thread addresses
    const int ldr = tid >> 2, ldc = tid & 3;          // loader coords (rows ldr, ldr+64... via h)
    const uint32_t ldoff0 = (uint32_t)(ldr * 64 + ((ldc ^ ((ldr >> 1) & 3)) << 4));
    const int ldr1 = ldr + 64;
    const uint32_t ldoff1 = (uint32_t)(ldr1 * 64 + ((ldc ^ ((ldr1 >> 1) & 3)) << 4));
    const __half* Abase = A + (size_t)(row0 + ldr) * K + ldc * 8;
    const __half* Abase1 = A + (size_t)(row0 + ldr1) * K + ldc * 8;
    const __half* Wbase = Wb + (size_t)(col0 + ldr) * K + ldc * 8;
    const __half* Wbase1 = Wb + (size_t)(col0 + ldr1) * K + ldc * 8;
    const int okA0 = (row0 + ldr) < M ? 16 : 0;
    const int okA1 = (row0 + ldr1) < M ? 16 : 0;

    auto load_tile = [&](int kt, int st) {
        uint32_t sa = sbase + st * 2 * TILE_B;
        uint32_t sb = sa + TILE_B;
        cp_async16(sa + ldoff0, Abase + kt * BK, okA0);
        cp_async16(sa + ldoff1, Abase1 + kt * BK, okA1);
        cp_async16(sb + ldoff0, Wbase + kt * BK, 16);
        cp_async16(sb + ldoff1, Wbase1 + kt * BK, 16);
        asm volatile("cp.async.commit_group;");
    };

    // hoisted fragment addresses (within a stage, per ks)
    uint32_t aoff[2][4], boff[2][2];
    #pragma unroll
    for (int ks = 0; ks < 2; ks++) {
        #pragma unroll
        for (int mf = 0; mf < 4; mf++) {
            int r = wm * 64 + mf * 16 + (lane & 15);
            int c = 2 * ks + (lane >> 4);
            aoff[ks][mf] = (uint32_t)(r * 64 + ((c ^ ((r >> 1) & 3)) << 4));
        }
        #pragma unroll
        for (int nfp = 0; nfp < 2; nfp++) {
            int r = wn * 32 + nfp * 16 + (lane & 7) + ((lane >> 4) & 1) * 8;
            int c = 2 * ks + ((lane >> 3) & 1);
            boff[ks][nfp] = (uint32_t)(r * 64 + ((c ^ ((r >> 1) & 3)) << 4));
        }
    }

    load_tile(0, 0);
    load_tile(1, 1);

    #pragma unroll
    for (int kt = 0; kt < nkt; kt++) {
        if (kt < nkt - 1) asm volatile("cp.async.wait_group 1;");
        else              asm volatile("cp.async.wait_group 0;");
        __syncthreads();
        if (kt + 2 < nkt) load_tile(kt + 2, (kt + 2) % STAGES);

        uint32_t sa = sbase + (kt % STAGES) * 2 * TILE_B;
        uint32_t sb = sa + TILE_B;
        #pragma unroll
        for (int ks = 0; ks < 2; ks++) {
            uint32_t aF[4][4], bF[2][4];
            #pragma unroll
            for (int mf = 0; mf < 4; mf++) ldsm_x4(aF[mf], sa + aoff[ks][mf]);
            #pragma unroll
            for (int nfp = 0; nfp < 2; nfp++) ldsm_x4(bF[nfp], sb + boff[ks][nfp]);
            #pragma unroll
            for (int mf = 0; mf < 4; mf++)
                #pragma unroll
                for (int nf = 0; nf < 4; nf++)
                    mma_f16h(accH[mf][nf], aF[mf],
                             bF[nf >> 1][(nf & 1) * 2], bF[nf >> 1][(nf & 1) * 2 + 1]);
        }
    }

    auto scatter_of = [](int r) -> size_t {
        int bw = r / 49, tok = r - bw * 49;
        int bb = bw / 49, wi = bw - bb * 49;
        int R  = (wi / 7) * 7 + tok / 7;
        int Cl = (wi % 7) * 7 + tok % 7;
        int rr = R + 3;  if (rr >= 49) rr -= 49;
        int cc = Cl + 3; if (cc >= 49) cc -= 49;
        return ((size_t)bb * 2401 + rr * 49 + cc) * 128;
    };

    if (EPI == 1) {
        #pragma unroll
        for (int mf = 0; mf < 4; mf++) {
            #pragma unroll
            for (int hh = 0; hh < 2; hh++) {
                int rl = wm * 64 + mf * 16 + g + hh * 8;
                int r = row0 + rl;
                bool ok = r < M;
                size_t dest = scatter_of(ok ? r : (M - 1));
                float s = 0.f, s2 = 0.f;
                #pragma unroll
                for (int nf = 0; nf < 4; nf++) {
                    int n = wn * 32 + nf * 8 + tg * 2;
                    __half2 hv = *reinterpret_cast<__half2*>(&accH[mf][nf][hh]);
                    float2 a2 = *reinterpret_cast<const float2*>(aux + dest + n);
                    float2 b2 = *reinterpret_cast<const float2*>(bias + n);
                    float2 v;
                    v.x = __low2float(hv)  + b2.x + a2.x;
                    v.y = __high2float(hv) + b2.y + a2.y;
                    if (ok) *reinterpret_cast<float2*>(g_x2 + dest + n) = v;
                    s  += v.x + v.y;
                    s2 += v.x * v.x + v.y * v.y;
                }
                s  += __shfl_xor_sync(0xffffffffu, s,  1);
                s2 += __shfl_xor_sync(0xffffffffu, s2, 1);
                s  += __shfl_xor_sync(0xffffffffu, s,  2);
                s2 += __shfl_xor_sync(0xffffffffu, s2, 2);
                if (tg == 0) {
                    sred[(rl * 4 + wn) * 2]     = s;
                    sred[(rl * 4 + wn) * 2 + 1] = s2;
                }
            }
        }
        __syncthreads();
        #pragma unroll
        for (int mf = 0; mf < 4; mf++) {
            #pragma unroll
            for (int hh = 0; hh < 2; hh++) {
                int rl = wm * 64 + mf * 16 + g + hh * 8;
                int r = row0 + rl;
                bool ok = r < M;
                size_t dest = scatter_of(ok ? r : (M - 1));
                float ts = 0.f, ts2 = 0.f;
                #pragma unroll
                for (int q = 0; q < 4; q++) {
                    ts  += sred[(rl * 4 + q) * 2];
                    ts2 += sred[(rl * 4 + q) * 2 + 1];
                }
                float mean = ts * (1.f / 128.f);
                float var  = ts2 * (1.f / 128.f) - mean * mean;
                float rstd = rsqrtf(var + 1e-5f);
                if (ok) {
                    #pragma unroll
                    for (int nf = 0; nf < 4; nf++) {
                        int n = wn * 32 + nf * 8 + tg * 2;
                        float2 v = *reinterpret_cast<const float2*>(g_x2 + dest + n);
                        float2 w2 = *reinterpret_cast<const float2*>(n2w + n);
                        float2 c2 = *reinterpret_cast<const float2*>(n2b + n);
                        __half2 o;
                        o.x = __float2half_rn((v.x - mean) * rstd * w2.x + c2.x);
                        o.y = __float2half_rn((v.y - mean) * rstd * w2.y + c2.y);
                        *reinterpret_cast<uint32_t*>(g_ln2 + dest + n) = *(uint32_t*)&o;
                    }
                }
            }
        }
    } else {
        #pragma unroll
        for (int mf = 0; mf < 4; mf++) {
            #pragma unroll
            for (int hh = 0; hh < 2; hh++) {
                int r = row0 + wm * 64 + mf * 16 + g + hh * 8;
                if (r >= M) continue;
                #pragma unroll
                for (int nf = 0; nf < 4; nf++) {
                    int n = col0 + wn * 32 + nf * 8 + tg * 2;
                    __half2 hv = *reinterpret_cast<__half2*>(&accH[mf][nf][hh]);
                    float2 b2 = *reinterpret_cast<const float2*>(bias + n);
                    float vx = __low2float(hv)  + b2.x;
                    float vy = __high2float(hv) + b2.y;
                    if (EPI == 0) {
                        __half2 o; o.x = __float2half_rn(vx); o.y = __float2half_rn(vy);
                        *reinterpret_cast<uint32_t*>(g_big + (size_t)r * 384 + n) = *(uint32_t*)&o;
                    } else if (EPI == 2) {
                        vx = 0.5f * vx * (1.f + erff(vx * 0.70710678118654752f));
                        vy = 0.5f * vy * (1.f + erff(vy * 0.70710678118654752f));
                        __half2 o; o.x = __float2half_rn(vx); o.y = __float2half_rn(vy);
                        *reinterpret_cast<uint32_t*>(g_big + (size_t)r * 512 + n) = *(uint32_t*)&o;
                    } else {
                        float2 x2v = *reinterpret_cast<const float2*>(g_x2 + (size_t)r * 128 + n);
                        float2 o; o.x = vx + x2v.x; o.y = vy + x2v.y;
                        *reinterpret_cast<float2*>(extC + (size_t)r * 128 + n) = o;
                    }
                }
            }
        }
    }
}

// ---------------- launch ----------------
extern "C" void kernel_launch(void* const* d_in, const int* in_sizes, int n_in,
                              void* d_out, int out_size) {
    const float* x      = (const float*)d_in[0];
    const float* n1w    = (const float*)d_in[1];
    const float* n1b    = (const float*)d_in[2];
    const float* qkv_w  = (const float*)d_in[3];
    const float* qkv_b  = (const float*)d_in[4];
    const float* proj_w = (const float*)d_in[5];
    const float* proj_b = (const float*)d_in[6];
    const float* rpb    = (const float*)d_in[7];
    const float* n2w    = (const float*)d_in[8];
    const float* n2b    = (const float*)d_in[9];
    const float* fc1_w  = (const float*)d_in[10];
    const float* fc1_b  = (const float*)d_in[11];
    const float* fc2_w  = (const float*)d_in[12];
    const float* fc2_b  = (const float*)d_in[13];
    float* out = (float*)d_out;

    const int M = MROWS;
    const int gm = (M + 127) / 128;   // 901

    cvt_weights<<<256, 256>>>(qkv_w, proj_w, fc1_w, fc2_w, qkv_b);
    build_bm<<<dim3(49, 4), 256>>>(rpb);
    ln1_gather_kernel<<<M, 128>>>(x, n1w, n1b);

    __half* wbase;
    float* qb;
    cudaGetSymbolAddress((void**)&wbase, g_wts);
    cudaGetSymbolAddress((void**)&qb, g_qkvb);

    mma_gemm<0, 128><<<dim3(gm, 3), 256>>>(wbase + WOFF_QKV, qb, nullptr, nullptr, nullptr, nullptr, M);
    attn_kernel<<<dim3(BN * NWIN, 4), 128>>>();
    mma_gemm<1, 128><<<dim3(gm, 1), 256>>>(wbase + WOFF_PROJ, proj_b, x, nullptr, n2w, n2b, M);
    mma_gemm<2, 128><<<dim3(gm, 4), 256>>>(wbase + WOFF_FC1, fc1_b, nullptr, nullptr, nullptr, nullptr, M);
    mma_gemm<3, 512><<<dim3(gm, 1), 256>>>(wbase + WOFF_FC2, fc2_b, nullptr, out, nullptr, nullptr, M);
}